// round 10
// baseline (speedup 1.0000x reference)
#include <cuda_runtime.h>
#include <cuda_fp16.h>
#include <cstdint>

#define BB 4
#define NSEQ 2048
#define CDIM 768
#define HNUM 12
#define DHEAD 64
#define QSE 0.18033688011112042f   // 0.125 * log2(e)

// ---------------- scratch ----------------
__device__ unsigned g_maskbits[NSEQ * (NSEQ / 32)];
__device__ int g_mask_mode;
__device__ __half g_xh[8192*768], g_xl[8192*768];
__device__ __half g_wqh[2304*768], g_wql[2304*768];
__device__ __half g_wph[768*768],  g_wpl[768*768];
// pre-split attention operands (written by gemm_qkv epilogue)
__device__ __half g_Qh[48*2048*64], g_Ql[48*2048*64];   // [bh][tok][d], scaled
__device__ __half g_Kh[48*2048*64], g_Kl[48*2048*64];   // [bh][tok][d]
__device__ __half g_Vh[48*64*2048], g_Vl[48*64*2048];   // [bh][d][tok]
__device__ __half g_Ch[8192*768],  g_Cl[8192*768];      // ctx hi/lo

// ---------------- helpers ----------------
__device__ __forceinline__ uint32_t smem_u32(const void* p){
    uint32_t a; asm("{ .reg .u64 t; cvta.to.shared.u64 t, %1; cvt.u32.u64 %0, t; }":"=r"(a):"l"(p)); return a;
}
__device__ __forceinline__ float ex2f(float x){ float r; asm("ex2.approx.f32 %0,%1;":"=f"(r):"f"(x)); return r; }
__device__ __forceinline__ uint32_t pk2(float a, float b){ __half2 h=__floats2half2_rn(a,b); return *(uint32_t*)&h; }

#define LDSM4(r0,r1,r2,r3,ad) asm volatile("ldmatrix.sync.aligned.m8n8.x4.shared.b16 {%0,%1,%2,%3},[%4];":"=r"(r0),"=r"(r1),"=r"(r2),"=r"(r3):"r"(ad))
#define MMA(d,a,b) asm volatile("mma.sync.aligned.m16n8k16.row.col.f32.f16.f16.f32 {%0,%1,%2,%3},{%4,%5,%6,%7},{%8,%9},{%0,%1,%2,%3};" \
    :"+f"((d)[0]),"+f"((d)[1]),"+f"((d)[2]),"+f"((d)[3]) \
    :"r"((a)[0]),"r"((a)[1]),"r"((a)[2]),"r"((a)[3]),"r"((b)[0]),"r"((b)[1]))

__device__ __forceinline__ void ldA(uint32_t* a, uint32_t base, int rb, int kc, int P){
    int l = threadIdx.x & 31;
    uint32_t ad = base + (uint32_t)((rb + (l&7) + ((l>>3)&1)*8)*P + kc + (l>>4)*8)*2;
    LDSM4(a[0],a[1],a[2],a[3],ad);
}
__device__ __forceinline__ void ldB(uint32_t* b, uint32_t base, int nb, int kc, int P){
    int l = threadIdx.x & 31;
    uint32_t ad = base + (uint32_t)((nb + (l&7) + (l>>4)*8)*P + kc + ((l>>3)&1)*8)*2;
    LDSM4(b[0],b[1],b[2],b[3],ad);
}

// ---------------- mask probe + pack ----------------
__global__ void probe_mask(const unsigned* __restrict__ mw) {
    __shared__ int s_not01, s_notfloat;
    int tid = threadIdx.x;
    if (tid == 0) { s_not01 = 0; s_notfloat = 0; }
    __syncthreads();
    unsigned v = mw[tid];
    if (v != 0u && v != 1u) s_not01 = 1;
    if (v != 0u && v != 0x3F800000u) s_notfloat = 1;
    __syncthreads();
    if (tid == 0) g_mask_mode = (!s_not01) ? 0 : (!s_notfloat ? 1 : 2);
}
__global__ void mask_pack(const void* __restrict__ mask) {
    int gid = blockIdx.x * 256 + threadIdx.x;
    if (gid >= NSEQ * (NSEQ / 32)) return;
    long base = (long)(gid >> 6) * NSEQ + (long)(gid & 63) * 32;
    int mode = g_mask_mode;
    unsigned bits = 0u;
    if (mode == 0) {
        const int* p = (const int*)mask;
        #pragma unroll
        for (int j = 0; j < 32; j++) if (p[base + j] != 0) bits |= (1u << j);
    } else if (mode == 1) {
        const float* p = (const float*)mask;
        #pragma unroll
        for (int j = 0; j < 32; j++) if (p[base + j] != 0.0f) bits |= (1u << j);
    } else {
        const unsigned char* p = (const unsigned char*)mask;
        #pragma unroll
        for (int j = 0; j < 32; j++) if (p[base + j] != 0) bits |= (1u << j);
    }
    g_maskbits[gid] = bits;
}

// ---------------- split inputs ----------------
__global__ void splitx(const float* __restrict__ x){
    size_t i = ((size_t)blockIdx.x*256 + threadIdx.x)*4;
    float4 v = *(const float4*)(x + i);
    __half h0=__float2half_rn(v.x), h1=__float2half_rn(v.y), h2=__float2half_rn(v.z), h3=__float2half_rn(v.w);
    g_xh[i]=h0; g_xh[i+1]=h1; g_xh[i+2]=h2; g_xh[i+3]=h3;
    g_xl[i]  =__float2half_rn(v.x-__half2float(h0));
    g_xl[i+1]=__float2half_rn(v.y-__half2float(h1));
    g_xl[i+2]=__float2half_rn(v.z-__half2float(h2));
    g_xl[i+3]=__float2half_rn(v.w-__half2float(h3));
}
__global__ void wsplit(const float* __restrict__ W, int K, int N, int sel){
    __shared__ float t[32][33];
    __half* Wh = sel ? g_wph : g_wqh;
    __half* Wl = sel ? g_wpl : g_wql;
    int k0 = blockIdx.y*32, n0 = blockIdx.x*32;
    int tx = threadIdx.x, ty = threadIdx.y;
    #pragma unroll
    for (int i=0;i<4;i++) t[ty+i*8][tx] = W[(size_t)(k0+ty+i*8)*N + n0+tx];
    __syncthreads();
    #pragma unroll
    for (int i=0;i<4;i++){
        float v = t[tx][ty+i*8];
        __half h = __float2half_rn(v);
        size_t o = (size_t)(n0+ty+i*8)*K + k0+tx;
        Wh[o] = h; Wl[o] = __float2half_rn(v - __half2float(h));
    }
}

// ---------------- HMMA qkv GEMM (proven mainloop; split epilogue) ----------
__global__ __launch_bounds__(256) void gemm_qkv(){
    __shared__ __half sm[9216];
    int tid = threadIdx.x, wid = tid>>5, lane = tid&31;
    int wm = wid>>1, wn = wid&1, gid = lane>>2, tig = lane&3;
    int m0 = blockIdx.y*128, n0 = blockIdx.x*64;
    uint32_t base = smem_u32(sm);
    float s[2][4][4];
    #pragma unroll
    for (int a=0;a<2;a++)
        #pragma unroll
        for (int b=0;b<4;b++)
            #pragma unroll
            for (int c=0;c<4;c++) s[a][b][c]=0.f;

    int arow = tid>>1, aseg = tid&1;
    const __half* pAh = g_xh + (size_t)(m0+arow)*768 + aseg*8;
    const __half* pAl = g_xl + (size_t)(m0+arow)*768 + aseg*8;
    int brow = (tid&127)>>1, bseg2 = tid&1;
    const __half* pB = (tid<128 ? g_wqh : g_wql) + (size_t)(n0+brow)*768 + bseg2*8;
    __half* dA = sm + arow*24 + aseg*8;
    __half* dB = sm + 6144 + (tid<128?0:1536) + brow*24 + bseg2*8;

    for (int k=0;k<48;k++){
        __syncthreads();
        *(uint4*)dA        = *(const uint4*)(pAh + k*16);
        *(uint4*)(dA+3072) = *(const uint4*)(pAl + k*16);
        *(uint4*)dB        = *(const uint4*)(pB  + k*16);
        __syncthreads();
        uint32_t ah[2][4], al[2][4], bh[8], bl[8];
        #pragma unroll
        for (int mt=0;mt<2;mt++){
            ldA(ah[mt], base,      wm*32+mt*16, 0, 24);
            ldA(al[mt], base+6144, wm*32+mt*16, 0, 24);
        }
        #pragma unroll
        for (int n2=0;n2<2;n2++){
            ldB(bh+n2*4, base+12288, wn*32+n2*16, 0, 24);
            ldB(bl+n2*4, base+15360, wn*32+n2*16, 0, 24);
        }
        #pragma unroll
        for (int mt=0;mt<2;mt++)
            #pragma unroll
            for (int nt=0;nt<4;nt++){
                MMA(s[mt][nt], ah[mt], bh+nt*2);
                MMA(s[mt][nt], al[mt], bh+nt*2);
                MMA(s[mt][nt], ah[mt], bl+nt*2);
            }
    }
    int which = n0/768, rem = n0 - which*768;
    int bhq = (m0>>11)*HNUM + (rem>>6);
    int tok0 = m0 & 2047;
    #pragma unroll
    for (int mt=0;mt<2;mt++)
        #pragma unroll
        for (int nt=0;nt<4;nt++)
            #pragma unroll
            for (int c=0;c<4;c++){
                int tok = tok0 + wm*32 + mt*16 + (c>>1)*8 + gid;
                int d = wn*32 + nt*8 + tig*2 + (c&1);
                float v = s[mt][nt][c];
                if (which==0){
                    v *= QSE;
                    __half h = __float2half_rn(v);
                    size_t o = ((size_t)bhq*NSEQ + tok)*DHEAD + d;
                    g_Qh[o]=h; g_Ql[o]=__float2half_rn(v-__half2float(h));
                } else if (which==1){
                    __half h = __float2half_rn(v);
                    size_t o = ((size_t)bhq*NSEQ + tok)*DHEAD + d;
                    g_Kh[o]=h; g_Kl[o]=__float2half_rn(v-__half2float(h));
                } else {
                    __half h = __float2half_rn(v);
                    size_t o = ((size_t)bhq*DHEAD + d)*NSEQ + tok;
                    g_Vh[o]=h; g_Vl[o]=__float2half_rn(v-__half2float(h));
                }
            }
}

// ---------------- HMMA proj GEMM: A = pre-split ctx ----------------
__global__ __launch_bounds__(256) void gemm_proj(const float* __restrict__ bias,
                                                 float* __restrict__ Out){
    __shared__ __half sm[9216];
    int tid = threadIdx.x, wid = tid>>5, lane = tid&31;
    int wm = wid>>1, wn = wid&1, gid = lane>>2, tig = lane&3;
    int m0 = blockIdx.y*128, n0 = blockIdx.x*64;
    uint32_t base = smem_u32(sm);
    float s[2][4][4];
    #pragma unroll
    for (int a=0;a<2;a++)
        #pragma unroll
        for (int b=0;b<4;b++)
            #pragma unroll
            for (int c=0;c<4;c++) s[a][b][c]=0.f;

    int arow = tid>>1, aseg = tid&1;
    const __half* pAh = g_Ch + (size_t)(m0+arow)*768 + aseg*8;
    const __half* pAl = g_Cl + (size_t)(m0+arow)*768 + aseg*8;
    int brow = (tid&127)>>1, bseg2 = tid&1;
    const __half* pB = (tid<128 ? g_wph : g_wpl) + (size_t)(n0+brow)*768 + bseg2*8;
    __half* dA = sm + arow*24 + aseg*8;
    __half* dB = sm + 6144 + (tid<128?0:1536) + brow*24 + bseg2*8;

    for (int k=0;k<48;k++){
        __syncthreads();
        *(uint4*)dA        = *(const uint4*)(pAh + k*16);
        *(uint4*)(dA+3072) = *(const uint4*)(pAl + k*16);
        *(uint4*)dB        = *(const uint4*)(pB  + k*16);
        __syncthreads();
        uint32_t ah[2][4], al[2][4], bh[8], bl[8];
        #pragma unroll
        for (int mt=0;mt<2;mt++){
            ldA(ah[mt], base,      wm*32+mt*16, 0, 24);
            ldA(al[mt], base+6144, wm*32+mt*16, 0, 24);
        }
        #pragma unroll
        for (int n2=0;n2<2;n2++){
            ldB(bh+n2*4, base+12288, wn*32+n2*16, 0, 24);
            ldB(bl+n2*4, base+15360, wn*32+n2*16, 0, 24);
        }
        #pragma unroll
        for (int mt=0;mt<2;mt++)
            #pragma unroll
            for (int nt=0;nt<4;nt++){
                MMA(s[mt][nt], ah[mt], bh+nt*2);
                MMA(s[mt][nt], al[mt], bh+nt*2);
                MMA(s[mt][nt], ah[mt], bl+nt*2);
            }
    }
    #pragma unroll
    for (int mt=0;mt<2;mt++)
        #pragma unroll
        for (int nt=0;nt<4;nt++)
            #pragma unroll
            for (int c=0;c<4;c++){
                int row = m0 + wm*32 + mt*16 + (c>>1)*8 + gid;
                int col = n0 + wn*32 + nt*8 + tig*2 + (c&1);
                Out[(size_t)row*768 + col] = s[mt][nt][c] + bias[col];
            }
}

// ---------------- HMMA attention (pre-split operands; copy-only staging) ---
// half offsets: Qh 0, Ql 9216, Kh 18432, Kl 23040, Vh 27648, Vl 32256, P 36864
#define ATTN_SMEM (92160)
__global__ __launch_bounds__(256) void attn_hm(){
    extern __shared__ __half sh[];
    uint32_t base = smem_u32(sh);
    int tid = threadIdx.x, wid = tid>>5, lane = tid&31;
    int wm = wid>>1, wn = wid&1, gid = lane>>2, tig = lane&3;
    int bh = blockIdx.y, b = bh/HNUM, hq = bh - b*HNUM;
    int row0 = blockIdx.x*128;

    // stage Q hi/lo [128][72] — pure copies (already scaled+split)
    {
        int arr = tid & 1, r = tid >> 1;
        const __half* src = (arr ? g_Ql : g_Qh) + ((size_t)bh*NSEQ + row0 + r)*DHEAD;
        __half* dst = sh + arr*9216 + r*72;
        #pragma unroll
        for (int i=0;i<8;i++) *(uint4*)(dst + i*8) = *(const uint4*)(src + i*8);
    }
    float o[2][4][4], ls[2][2];
    #pragma unroll
    for (int mt=0;mt<2;mt++){ ls[mt][0]=0.f; ls[mt][1]=0.f;
        #pragma unroll
        for (int nt=0;nt<4;nt++)
            #pragma unroll
            for (int c=0;c<4;c++) o[mt][nt][c]=0.f; }
    const unsigned* mp[2][2];
    #pragma unroll
    for (int mt=0;mt<2;mt++)
        #pragma unroll
        for (int rh=0;rh<2;rh++)
            mp[mt][rh] = g_maskbits + (size_t)(row0 + wm*32 + mt*16 + rh*8 + gid)*64 + wn;

    for (int t=0;t<32;t++){
        __syncthreads();
        {   // stage K hi/lo [64][72] + V hi/lo [64][72] — pure copies
            int blk = tid>>6, r = tid&63;
            const __half* src;
            __half* dst;
            if (blk==0){ src = g_Kh + ((size_t)bh*NSEQ + t*64 + r)*DHEAD; dst = sh + 18432 + r*72; }
            else if (blk==1){ src = g_Kl + ((size_t)bh*NSEQ + t*64 + r)*DHEAD; dst = sh + 23040 + r*72; }
            else if (blk==2){ src = g_Vh + ((size_t)bh*DHEAD + r)*NSEQ + t*64; dst = sh + 27648 + r*72; }
            else            { src = g_Vl + ((size_t)bh*DHEAD + r)*NSEQ + t*64; dst = sh + 32256 + r*72; }
            #pragma unroll
            for (int i=0;i<8;i++) *(uint4*)(dst + i*8) = *(const uint4*)(src + i*8);
        }
        __syncthreads();
        // S = Q K^T (hh + lh + hl)
        float s[2][4][4];
        #pragma unroll
        for (int mt=0;mt<2;mt++)
            #pragma unroll
            for (int nt=0;nt<4;nt++)
                #pragma unroll
                for (int c=0;c<4;c++) s[mt][nt][c]=0.f;
        #pragma unroll
        for (int ks=0;ks<4;ks++){
            uint32_t qh[2][4], ql[2][4], kh[8], kl[8];
            #pragma unroll
            for (int mt=0;mt<2;mt++){
                ldA(qh[mt], base,       wm*32+mt*16, ks*16, 72);
                ldA(ql[mt], base+18432, wm*32+mt*16, ks*16, 72);
            }
            #pragma unroll
            for (int n2=0;n2<2;n2++){
                ldB(kh+n2*4, base+36864, wn*32+n2*16, ks*16, 72);
                ldB(kl+n2*4, base+46080, wn*32+n2*16, ks*16, 72);
            }
            #pragma unroll
            for (int mt=0;mt<2;mt++)
                #pragma unroll
                for (int nt=0;nt<4;nt++){
                    MMA(s[mt][nt], qh[mt], kh+nt*2);
                    MMA(s[mt][nt], ql[mt], kh+nt*2);
                    MMA(s[mt][nt], qh[mt], kl+nt*2);
                }
        }
        // mask + exp2 (clamped) + P to smem + partial row sums
        #pragma unroll
        for (int mt=0;mt<2;mt++){
            unsigned w0 = mp[mt][0][t*2];
            unsigned w1 = mp[mt][1][t*2];
            int r0 = wm*32 + mt*16 + gid;
            #pragma unroll
            for (int nt=0;nt<4;nt++){
                int bb = nt*8 + tig*2;
                float p0 = ((w0>>bb)&1u)     ? 0.f : ex2f(fminf(s[mt][nt][0],14.f));
                float p1 = ((w0>>(bb+1))&1u) ? 0.f : ex2f(fminf(s[mt][nt][1],14.f));
                float p2 = ((w1>>bb)&1u)     ? 0.f : ex2f(fminf(s[mt][nt][2],14.f));
                float p3 = ((w1>>(bb+1))&1u) ? 0.f : ex2f(fminf(s[mt][nt][3],14.f));
                ls[mt][0] += p0+p1; ls[mt][1] += p2+p3;
                int col = wn*32 + nt*8 + tig*2;
                *(uint32_t*)(sh + 36864 + r0*72 + col)     = pk2(p0,p1);
                *(uint32_t*)(sh + 36864 + (r0+8)*72 + col) = pk2(p2,p3);
            }
        }
        __syncthreads();
        // O += P V (P single-rounded, V split)
        #pragma unroll
        for (int ks=0;ks<4;ks++){
            uint32_t pa[2][4], vh[8], vl[8];
            #pragma unroll
            for (int mt=0;mt<2;mt++)
                ldA(pa[mt], base+73728, wm*32+mt*16, ks*16, 72);
            #pragma unroll
            for (int n2=0;n2<2;n2++){
                ldB(vh+n2*4, base+55296, wn*32+n2*16, ks*16, 72);
                ldB(vl+n2*4, base+64512, wn*32+n2*16, ks*16, 72);
            }
            #pragma unroll
            for (int mt=0;mt<2;mt++)
                #pragma unroll
                for (int nt=0;nt<4;nt++){
                    MMA(o[mt][nt], pa[mt], vh+nt*2);
                    MMA(o[mt][nt], pa[mt], vl+nt*2);
                }
        }
    }
    // row sums: tig lanes then cross-wn via smem
    #pragma unroll
    for (int mt=0;mt<2;mt++)
        #pragma unroll
        for (int rh=0;rh<2;rh++){
            ls[mt][rh] += __shfl_xor_sync(0xffffffffu, ls[mt][rh], 1);
            ls[mt][rh] += __shfl_xor_sync(0xffffffffu, ls[mt][rh], 2);
        }
    __syncthreads();
    float* lbuf = (float*)sh;
    if (tig==0){
        #pragma unroll
        for (int mt=0;mt<2;mt++)
            #pragma unroll
            for (int rh=0;rh<2;rh++)
                lbuf[wn*128 + wm*32 + mt*16 + rh*8 + gid] = ls[mt][rh];
    }
    __syncthreads();
    float inv[2][2];
    #pragma unroll
    for (int mt=0;mt<2;mt++)
        #pragma unroll
        for (int rh=0;rh<2;rh++){
            int r = wm*32 + mt*16 + rh*8 + gid;
            inv[mt][rh] = 1.0f / fmaxf(lbuf[r] + lbuf[128+r], 1e-30f);
        }
    #pragma unroll
    for (int mt=0;mt<2;mt++)
        #pragma unroll
        for (int nt=0;nt<4;nt++)
            #pragma unroll
            for (int c=0;c<4;c++){
                float v = o[mt][nt][c]*inv[mt][c>>1];
                int row = row0 + wm*32 + mt*16 + (c>>1)*8 + gid;
                int d = wn*32 + nt*8 + tig*2 + (c&1);
                size_t off = ((size_t)b*NSEQ + row)*CDIM + hq*64 + d;
                __half h = __float2half_rn(v);
                g_Ch[off] = h; g_Cl[off] = __float2half_rn(v - __half2float(h));
            }
}

// ---------------- launch ----------------
extern "C" void kernel_launch(void* const* d_in, const int* in_sizes, int n_in,
                              void* d_out, int out_size){
    const float* x      = (const float*)d_in[0];
    const void*  mask   = d_in[1];
    const float* w_qkv  = (const float*)d_in[2];
    const float* w_proj = (const float*)d_in[3];
    const float* b_proj = (const float*)d_in[4];
    float* out = (float*)d_out;

    cudaFuncSetAttribute(attn_hm, cudaFuncAttributeMaxDynamicSharedMemorySize, ATTN_SMEM);

    probe_mask<<<1, 256>>>((const unsigned*)mask);
    mask_pack<<<512, 256>>>(mask);
    splitx<<<6144, 256>>>(x);
    wsplit<<<dim3(72,24), dim3(32,8)>>>(w_qkv, 768, 2304, 0);
    wsplit<<<dim3(24,24), dim3(32,8)>>>(w_proj, 768, 768, 1);
    gemm_qkv<<<dim3(36,64), 256>>>();
    attn_hm<<<dim3(16,48), 256, ATTN_SMEM>>>();
    gemm_proj<<<dim3(12,64), 256>>>(b_proj, out);
}

// round 11
// speedup vs baseline: 1.3075x; 1.3075x over previous
#include <cuda_runtime.h>
#include <cuda_fp16.h>
#include <cstdint>

#define BB 4
#define NSEQ 2048
#define CDIM 768
#define HNUM 12
#define DHEAD 64
#define QSE 0.18033688011112042f   // 0.125 * log2(e)

// ---------------- scratch ----------------
__device__ unsigned g_maskbits[NSEQ * (NSEQ / 32)];
__device__ int g_mask_mode;
__device__ __half g_xh[8192*768], g_xl[8192*768];
__device__ __half g_wqh[2304*768], g_wql[2304*768];
__device__ __half g_wph[768*768],  g_wpl[768*768];
__device__ __half g_Qh[48*2048*64], g_Ql[48*2048*64];   // [bh][tok][d], scaled
__device__ __half g_Kh[48*2048*64], g_Kl[48*2048*64];   // [bh][tok][d]
__device__ __half g_Vh[48*64*2048], g_Vl[48*64*2048];   // [bh][d][tok]
__device__ __half g_Ch[8192*768],  g_Cl[8192*768];      // ctx hi/lo

// ---------------- helpers ----------------
__device__ __forceinline__ uint32_t smem_u32(const void* p){
    uint32_t a; asm("{ .reg .u64 t; cvta.to.shared.u64 t, %1; cvt.u32.u64 %0, t; }":"=r"(a):"l"(p)); return a;
}
__device__ __forceinline__ float ex2f(float x){ float r; asm("ex2.approx.f32 %0,%1;":"=f"(r):"f"(x)); return r; }
__device__ __forceinline__ uint32_t pk2(float a, float b){ __half2 h=__floats2half2_rn(a,b); return *(uint32_t*)&h; }

#define CPA16(dst, src) asm volatile("cp.async.cg.shared.global [%0], [%1], 16;\n"::"r"(dst),"l"(src):"memory")
#define CPA_COMMIT()    asm volatile("cp.async.commit_group;\n":::"memory")
#define CPA_WAIT0()     asm volatile("cp.async.wait_group 0;\n":::"memory")

#define LDSM4(r0,r1,r2,r3,ad) asm volatile("ldmatrix.sync.aligned.m8n8.x4.shared.b16 {%0,%1,%2,%3},[%4];":"=r"(r0),"=r"(r1),"=r"(r2),"=r"(r3):"r"(ad))
#define MMA(d,a,b) asm volatile("mma.sync.aligned.m16n8k16.row.col.f32.f16.f16.f32 {%0,%1,%2,%3},{%4,%5,%6,%7},{%8,%9},{%0,%1,%2,%3};" \
    :"+f"((d)[0]),"+f"((d)[1]),"+f"((d)[2]),"+f"((d)[3]) \
    :"r"((a)[0]),"r"((a)[1]),"r"((a)[2]),"r"((a)[3]),"r"((b)[0]),"r"((b)[1]))

__device__ __forceinline__ void ldA(uint32_t* a, uint32_t base, int rb, int kc, int P){
    int l = threadIdx.x & 31;
    uint32_t ad = base + (uint32_t)((rb + (l&7) + ((l>>3)&1)*8)*P + kc + (l>>4)*8)*2;
    LDSM4(a[0],a[1],a[2],a[3],ad);
}
__device__ __forceinline__ void ldB(uint32_t* b, uint32_t base, int nb, int kc, int P){
    int l = threadIdx.x & 31;
    uint32_t ad = base + (uint32_t)((nb + (l&7) + (l>>4)*8)*P + kc + ((l>>3)&1)*8)*2;
    LDSM4(b[0],b[1],b[2],b[3],ad);
}

// ---------------- mask probe + pack ----------------
__global__ void probe_mask(const unsigned* __restrict__ mw) {
    __shared__ int s_not01, s_notfloat;
    int tid = threadIdx.x;
    if (tid == 0) { s_not01 = 0; s_notfloat = 0; }
    __syncthreads();
    unsigned v = mw[tid];
    if (v != 0u && v != 1u) s_not01 = 1;
    if (v != 0u && v != 0x3F800000u) s_notfloat = 1;
    __syncthreads();
    if (tid == 0) g_mask_mode = (!s_not01) ? 0 : (!s_notfloat ? 1 : 2);
}
__global__ void mask_pack(const void* __restrict__ mask) {
    int gid = blockIdx.x * 256 + threadIdx.x;
    if (gid >= NSEQ * (NSEQ / 32)) return;
    long base = (long)(gid >> 6) * NSEQ + (long)(gid & 63) * 32;
    int mode = g_mask_mode;
    unsigned bits = 0u;
    if (mode == 0) {
        const int* p = (const int*)mask;
        #pragma unroll
        for (int j = 0; j < 32; j++) if (p[base + j] != 0) bits |= (1u << j);
    } else if (mode == 1) {
        const float* p = (const float*)mask;
        #pragma unroll
        for (int j = 0; j < 32; j++) if (p[base + j] != 0.0f) bits |= (1u << j);
    } else {
        const unsigned char* p = (const unsigned char*)mask;
        #pragma unroll
        for (int j = 0; j < 32; j++) if (p[base + j] != 0) bits |= (1u << j);
    }
    g_maskbits[gid] = bits;
}

// ---------------- split inputs ----------------
__global__ void splitx(const float* __restrict__ x){
    size_t i = ((size_t)blockIdx.x*256 + threadIdx.x)*4;
    float4 v = *(const float4*)(x + i);
    __half h0=__float2half_rn(v.x), h1=__float2half_rn(v.y), h2=__float2half_rn(v.z), h3=__float2half_rn(v.w);
    g_xh[i]=h0; g_xh[i+1]=h1; g_xh[i+2]=h2; g_xh[i+3]=h3;
    g_xl[i]  =__float2half_rn(v.x-__half2float(h0));
    g_xl[i+1]=__float2half_rn(v.y-__half2float(h1));
    g_xl[i+2]=__float2half_rn(v.z-__half2float(h2));
    g_xl[i+3]=__float2half_rn(v.w-__half2float(h3));
}
__global__ void wsplit(const float* __restrict__ W, int K, int N, int sel){
    __shared__ float t[32][33];
    __half* Wh = sel ? g_wph : g_wqh;
    __half* Wl = sel ? g_wpl : g_wql;
    int k0 = blockIdx.y*32, n0 = blockIdx.x*32;
    int tx = threadIdx.x, ty = threadIdx.y;
    #pragma unroll
    for (int i=0;i<4;i++) t[ty+i*8][tx] = W[(size_t)(k0+ty+i*8)*N + n0+tx];
    __syncthreads();
    #pragma unroll
    for (int i=0;i<4;i++){
        float v = t[tx][ty+i*8];
        __half h = __float2half_rn(v);
        size_t o = (size_t)(n0+ty+i*8)*K + k0+tx;
        Wh[o] = h; Wl[o] = __float2half_rn(v - __half2float(h));
    }
}

// ---------------- HMMA qkv GEMM: cp.async double-buffered ----------------
__global__ __launch_bounds__(256) void gemm_qkv(){
    __shared__ __half sm[2*9216];
    int tid = threadIdx.x, wid = tid>>5, lane = tid&31;
    int wm = wid>>1, wn = wid&1, gid = lane>>2, tig = lane&3;
    int m0 = blockIdx.y*128, n0 = blockIdx.x*64;
    uint32_t base = smem_u32(sm);
    float s[2][4][4];
    #pragma unroll
    for (int a=0;a<2;a++)
        #pragma unroll
        for (int b=0;b<4;b++)
            #pragma unroll
            for (int c=0;c<4;c++) s[a][b][c]=0.f;

    int arow = tid>>1, aseg = tid&1;
    const __half* pAh = g_xh + (size_t)(m0+arow)*768 + aseg*8;
    const __half* pAl = g_xl + (size_t)(m0+arow)*768 + aseg*8;
    int brow = (tid&127)>>1, bseg2 = tid&1;
    const __half* pB = (tid<128 ? g_wqh : g_wql) + (size_t)(n0+brow)*768 + bseg2*8;
    uint32_t dA  = base + (uint32_t)(arow*24 + aseg*8)*2;
    uint32_t dAl = dA + 6144;
    uint32_t dB  = base + 12288u + (tid<128?0u:3072u) + (uint32_t)(brow*24 + bseg2*8)*2;

    CPA16(dA, pAh); CPA16(dAl, pAl); CPA16(dB, pB);
    CPA_COMMIT();
    for (int k=0;k<48;k++){
        uint32_t bb = (uint32_t)(k&1)*18432u;
        CPA_WAIT0();
        __syncthreads();
        if (k<47){
            uint32_t nb = (uint32_t)((k+1)&1)*18432u;
            CPA16(dA+nb, pAh+(k+1)*16); CPA16(dAl+nb, pAl+(k+1)*16); CPA16(dB+nb, pB+(k+1)*16);
            CPA_COMMIT();
        }
        uint32_t ah[2][4], al[2][4], bh[8], bl[8];
        #pragma unroll
        for (int mt=0;mt<2;mt++){
            ldA(ah[mt], base+bb,      wm*32+mt*16, 0, 24);
            ldA(al[mt], base+bb+6144, wm*32+mt*16, 0, 24);
        }
        #pragma unroll
        for (int n2=0;n2<2;n2++){
            ldB(bh+n2*4, base+bb+12288, wn*32+n2*16, 0, 24);
            ldB(bl+n2*4, base+bb+15360, wn*32+n2*16, 0, 24);
        }
        #pragma unroll
        for (int mt=0;mt<2;mt++)
            #pragma unroll
            for (int nt=0;nt<4;nt++){
                MMA(s[mt][nt], ah[mt], bh+nt*2);
                MMA(s[mt][nt], al[mt], bh+nt*2);
                MMA(s[mt][nt], ah[mt], bl+nt*2);
            }
        __syncthreads();
    }
    int which = n0/768, rem = n0 - which*768;
    int bhq = (m0>>11)*HNUM + (rem>>6);
    int tok0 = m0 & 2047;
    #pragma unroll
    for (int mt=0;mt<2;mt++)
        #pragma unroll
        for (int nt=0;nt<4;nt++){
            int d0 = wn*32 + nt*8 + tig*2;
            if (which==2){
                #pragma unroll
                for (int c=0;c<4;c++){
                    int tok = tok0 + wm*32 + mt*16 + (c>>1)*8 + gid;
                    int d = d0 + (c&1);
                    float v = s[mt][nt][c];
                    __half h = __float2half_rn(v);
                    size_t o = ((size_t)bhq*DHEAD + d)*NSEQ + tok;
                    g_Vh[o]=h; g_Vl[o]=__float2half_rn(v-__half2float(h));
                }
            } else {
                float sc = (which==0) ? QSE : 1.0f;
                __half* Ah = (which==0) ? g_Qh : g_Kh;
                __half* Al = (which==0) ? g_Ql : g_Kl;
                #pragma unroll
                for (int rh=0;rh<2;rh++){
                    int tok = tok0 + wm*32 + mt*16 + rh*8 + gid;
                    float v0 = s[mt][nt][rh*2+0]*sc, v1 = s[mt][nt][rh*2+1]*sc;
                    __half h0=__float2half_rn(v0), h1=__float2half_rn(v1);
                    size_t o = ((size_t)bhq*NSEQ + tok)*DHEAD + d0;
                    *(uint32_t*)(Ah+o) = pk2(v0,v1);
                    *(uint32_t*)(Al+o) = pk2(v0-__half2float(h0), v1-__half2float(h1));
                }
            }
        }
}

// ---------------- HMMA proj GEMM: cp.async double-buffered ----------------
__global__ __launch_bounds__(256) void gemm_proj(const float* __restrict__ bias,
                                                 float* __restrict__ Out){
    __shared__ __half sm[2*9216];
    int tid = threadIdx.x, wid = tid>>5, lane = tid&31;
    int wm = wid>>1, wn = wid&1, gid = lane>>2, tig = lane&3;
    int m0 = blockIdx.y*128, n0 = blockIdx.x*64;
    uint32_t base = smem_u32(sm);
    float s[2][4][4];
    #pragma unroll
    for (int a=0;a<2;a++)
        #pragma unroll
        for (int b=0;b<4;b++)
            #pragma unroll
            for (int c=0;c<4;c++) s[a][b][c]=0.f;

    int arow = tid>>1, aseg = tid&1;
    const __half* pAh = g_Ch + (size_t)(m0+arow)*768 + aseg*8;
    const __half* pAl = g_Cl + (size_t)(m0+arow)*768 + aseg*8;
    int brow = (tid&127)>>1, bseg2 = tid&1;
    const __half* pB = (tid<128 ? g_wph : g_wpl) + (size_t)(n0+brow)*768 + bseg2*8;
    uint32_t dA  = base + (uint32_t)(arow*24 + aseg*8)*2;
    uint32_t dAl = dA + 6144;
    uint32_t dB  = base + 12288u + (tid<128?0u:3072u) + (uint32_t)(brow*24 + bseg2*8)*2;

    CPA16(dA, pAh); CPA16(dAl, pAl); CPA16(dB, pB);
    CPA_COMMIT();
    for (int k=0;k<48;k++){
        uint32_t bb = (uint32_t)(k&1)*18432u;
        CPA_WAIT0();
        __syncthreads();
        if (k<47){
            uint32_t nb = (uint32_t)((k+1)&1)*18432u;
            CPA16(dA+nb, pAh+(k+1)*16); CPA16(dAl+nb, pAl+(k+1)*16); CPA16(dB+nb, pB+(k+1)*16);
            CPA_COMMIT();
        }
        uint32_t ah[2][4], al[2][4], bh[8], bl[8];
        #pragma unroll
        for (int mt=0;mt<2;mt++){
            ldA(ah[mt], base+bb,      wm*32+mt*16, 0, 24);
            ldA(al[mt], base+bb+6144, wm*32+mt*16, 0, 24);
        }
        #pragma unroll
        for (int n2=0;n2<2;n2++){
            ldB(bh+n2*4, base+bb+12288, wn*32+n2*16, 0, 24);
            ldB(bl+n2*4, base+bb+15360, wn*32+n2*16, 0, 24);
        }
        #pragma unroll
        for (int mt=0;mt<2;mt++)
            #pragma unroll
            for (int nt=0;nt<4;nt++){
                MMA(s[mt][nt], ah[mt], bh+nt*2);
                MMA(s[mt][nt], al[mt], bh+nt*2);
                MMA(s[mt][nt], ah[mt], bl+nt*2);
            }
        __syncthreads();
    }
    #pragma unroll
    for (int mt=0;mt<2;mt++)
        #pragma unroll
        for (int nt=0;nt<4;nt++)
            #pragma unroll
            for (int c=0;c<4;c++){
                int row = m0 + wm*32 + mt*16 + (c>>1)*8 + gid;
                int col = n0 + wn*32 + nt*8 + tig*2 + (c&1);
                Out[(size_t)row*768 + col] = s[mt][nt][c] + bias[col];
            }
}

// ---------------- HMMA attention: cp.async double-buffered KV -------------
// byte layout: Qh 0, Ql 18432, KVbuf0 36864, KVbuf1 73728, P 110592
//   each KV buf: Kh +0, Kl +9216, Vh +18432, Vl +27648  (64x72 halves each)
#define ATTN_SMEM (129024)
__global__ __launch_bounds__(256) void attn_hm(){
    extern __shared__ __half sh[];
    uint32_t base = smem_u32(sh);
    int tid = threadIdx.x, wid = tid>>5, lane = tid&31;
    int wm = wid>>1, wn = wid&1, gid = lane>>2, tig = lane&3;
    int bh = blockIdx.y, b = bh/HNUM, hq = bh - b*HNUM;
    int row0 = blockIdx.x*128;

    // stage Q hi/lo via cp.async
    #pragma unroll
    for (int i=0;i<8;i++){
        int id = tid + i*256;
        int arr = id>>10, rem = id&1023, r = rem>>3, seg = rem&7;
        const __half* src = (arr ? g_Ql : g_Qh) + ((size_t)bh*NSEQ + row0 + r)*DHEAD + seg*8;
        CPA16(base + (uint32_t)(arr*18432 + r*144 + seg*16), src);
    }
    // stage KV tile 0 into buf0
    #pragma unroll
    for (int i=0;i<8;i++){
        int id = tid + i*256;
        int arr = id>>9, rem = id&511, r = rem>>3, seg = rem&7;
        const __half* src;
        if (arr==0)      src = g_Kh + ((size_t)bh*NSEQ + r)*DHEAD + seg*8;
        else if (arr==1) src = g_Kl + ((size_t)bh*NSEQ + r)*DHEAD + seg*8;
        else if (arr==2) src = g_Vh + ((size_t)bh*DHEAD + r)*NSEQ + seg*8;
        else             src = g_Vl + ((size_t)bh*DHEAD + r)*NSEQ + seg*8;
        CPA16(base + (uint32_t)(36864 + arr*9216 + r*144 + seg*16), src);
    }
    CPA_COMMIT();

    float o[2][4][4], ls[2][2];
    #pragma unroll
    for (int mt=0;mt<2;mt++){ ls[mt][0]=0.f; ls[mt][1]=0.f;
        #pragma unroll
        for (int nt=0;nt<4;nt++)
            #pragma unroll
            for (int c=0;c<4;c++) o[mt][nt][c]=0.f; }
    const unsigned* mp[2][2];
    #pragma unroll
    for (int mt=0;mt<2;mt++)
        #pragma unroll
        for (int rh=0;rh<2;rh++)
            mp[mt][rh] = g_maskbits + (size_t)(row0 + wm*32 + mt*16 + rh*8 + gid)*64 + wn;

    CPA_WAIT0();
    __syncthreads();

    for (int t=0;t<32;t++){
        uint32_t cb = 36864u + (uint32_t)(t&1)*36864u;
        if (t<31){
            uint32_t nb = 36864u + (uint32_t)((t+1)&1)*36864u;
            #pragma unroll
            for (int i=0;i<8;i++){
                int id = tid + i*256;
                int arr = id>>9, rem = id&511, r = rem>>3, seg = rem&7;
                const __half* src;
                if (arr==0)      src = g_Kh + ((size_t)bh*NSEQ + (t+1)*64 + r)*DHEAD + seg*8;
                else if (arr==1) src = g_Kl + ((size_t)bh*NSEQ + (t+1)*64 + r)*DHEAD + seg*8;
                else if (arr==2) src = g_Vh + ((size_t)bh*DHEAD + r)*NSEQ + (t+1)*64 + seg*8;
                else             src = g_Vl + ((size_t)bh*DHEAD + r)*NSEQ + (t+1)*64 + seg*8;
                CPA16(base + nb + (uint32_t)(arr*9216 + r*144 + seg*16), src);
            }
            CPA_COMMIT();
        }
        // S = Q K^T (hh + lh + hl)
        float s[2][4][4];
        #pragma unroll
        for (int mt=0;mt<2;mt++)
            #pragma unroll
            for (int nt=0;nt<4;nt++)
                #pragma unroll
                for (int c=0;c<4;c++) s[mt][nt][c]=0.f;
        #pragma unroll
        for (int ks=0;ks<4;ks++){
            uint32_t qh[2][4], ql[2][4], kh[8], kl[8];
            #pragma unroll
            for (int mt=0;mt<2;mt++){
                ldA(qh[mt], base,       wm*32+mt*16, ks*16, 72);
                ldA(ql[mt], base+18432, wm*32+mt*16, ks*16, 72);
            }
            #pragma unroll
            for (int n2=0;n2<2;n2++){
                ldB(kh+n2*4, base+cb,      wn*32+n2*16, ks*16, 72);
                ldB(kl+n2*4, base+cb+9216, wn*32+n2*16, ks*16, 72);
            }
            #pragma unroll
            for (int mt=0;mt<2;mt++)
                #pragma unroll
                for (int nt=0;nt<4;nt++){
                    MMA(s[mt][nt], qh[mt], kh+nt*2);
                    MMA(s[mt][nt], ql[mt], kh+nt*2);
                    MMA(s[mt][nt], qh[mt], kl+nt*2);
                }
        }
        // mask + exp2 (clamped) + P to smem + partial row sums
        #pragma unroll
        for (int mt=0;mt<2;mt++){
            unsigned w0 = mp[mt][0][t*2];
            unsigned w1 = mp[mt][1][t*2];
            int r0 = wm*32 + mt*16 + gid;
            #pragma unroll
            for (int nt=0;nt<4;nt++){
                int bb = nt*8 + tig*2;
                float p0 = ((w0>>bb)&1u)     ? 0.f : ex2f(fminf(s[mt][nt][0],14.f));
                float p1 = ((w0>>(bb+1))&1u) ? 0.f : ex2f(fminf(s[mt][nt][1],14.f));
                float p2 = ((w1>>bb)&1u)     ? 0.f : ex2f(fminf(s[mt][nt][2],14.f));
                float p3 = ((w1>>(bb+1))&1u) ? 0.f : ex2f(fminf(s[mt][nt][3],14.f));
                ls[mt][0] += p0+p1; ls[mt][1] += p2+p3;
                int col = wn*32 + nt*8 + tig*2;
                *(uint32_t*)(sh + 55296 + r0*72 + col)     = pk2(p0,p1);
                *(uint32_t*)(sh + 55296 + (r0+8)*72 + col) = pk2(p2,p3);
            }
        }
        __syncthreads();
        // O += P V (P single-rounded, V split)
        #pragma unroll
        for (int ks=0;ks<4;ks++){
            uint32_t pa[2][4], vh[8], vl[8];
            #pragma unroll
            for (int mt=0;mt<2;mt++)
                ldA(pa[mt], base+110592, wm*32+mt*16, ks*16, 72);
            #pragma unroll
            for (int n2=0;n2<2;n2++){
                ldB(vh+n2*4, base+cb+18432, wn*32+n2*16, ks*16, 72);
                ldB(vl+n2*4, base+cb+27648, wn*32+n2*16, ks*16, 72);
            }
            #pragma unroll
            for (int mt=0;mt<2;mt++)
                #pragma unroll
                for (int nt=0;nt<4;nt++){
                    MMA(o[mt][nt], pa[mt], vh+nt*2);
                    MMA(o[mt][nt], pa[mt], vl+nt*2);
                }
        }
        if (t<31) CPA_WAIT0();
        __syncthreads();
    }
    // row sums: tig lanes then cross-wn via smem
    #pragma unroll
    for (int mt=0;mt<2;mt++)
        #pragma unroll
        for (int rh=0;rh<2;rh++){
            ls[mt][rh] += __shfl_xor_sync(0xffffffffu, ls[mt][rh], 1);
            ls[mt][rh] += __shfl_xor_sync(0xffffffffu, ls[mt][rh], 2);
        }
    float* lbuf = (float*)sh;
    if (tig==0){
        #pragma unroll
        for (int mt=0;mt<2;mt++)
            #pragma unroll
            for (int rh=0;rh<2;rh++)
                lbuf[wn*128 + wm*32 + mt*16 + rh*8 + gid] = ls[mt][rh];
    }
    __syncthreads();
    float inv[2][2];
    #pragma unroll
    for (int mt=0;mt<2;mt++)
        #pragma unroll
        for (int rh=0;rh<2;rh++){
            int r = wm*32 + mt*16 + rh*8 + gid;
            inv[mt][rh] = 1.0f / fmaxf(lbuf[r] + lbuf[128+r], 1e-30f);
        }
    #pragma unroll
    for (int mt=0;mt<2;mt++)
        #pragma unroll
        for (int nt=0;nt<4;nt++){
            int d0 = wn*32 + nt*8 + tig*2;
            #pragma unroll
            for (int rh=0;rh<2;rh++){
                float v0 = o[mt][nt][rh*2+0]*inv[mt][rh];
                float v1 = o[mt][nt][rh*2+1]*inv[mt][rh];
                int row = row0 + wm*32 + mt*16 + rh*8 + gid;
                size_t off = ((size_t)b*NSEQ + row)*CDIM + hq*64 + d0;
                __half h0 = __float2half_rn(v0), h1 = __float2half_rn(v1);
                *(uint32_t*)(g_Ch+off) = pk2(v0,v1);
                *(uint32_t*)(g_Cl+off) = pk2(v0-__half2float(h0), v1-__half2float(h1));
            }
        }
}

// ---------------- launch ----------------
extern "C" void kernel_launch(void* const* d_in, const int* in_sizes, int n_in,
                              void* d_out, int out_size){
    const float* x      = (const float*)d_in[0];
    const void*  mask   = d_in[1];
    const float* w_qkv  = (const float*)d_in[2];
    const float* w_proj = (const float*)d_in[3];
    const float* b_proj = (const float*)d_in[4];
    float* out = (float*)d_out;

    cudaFuncSetAttribute(attn_hm, cudaFuncAttributeMaxDynamicSharedMemorySize, ATTN_SMEM);

    probe_mask<<<1, 256>>>((const unsigned*)mask);
    mask_pack<<<512, 256>>>(mask);
    splitx<<<6144, 256>>>(x);
    wsplit<<<dim3(72,24), dim3(32,8)>>>(w_qkv, 768, 2304, 0);
    wsplit<<<dim3(24,24), dim3(32,8)>>>(w_proj, 768, 768, 1);
    gemm_qkv<<<dim3(36,64), 256>>>();
    attn_hm<<<dim3(16,48), 256, ATTN_SMEM>>>();
    gemm_proj<<<dim3(12,64), 256>>>(b_proj, out);
}

// round 12
// speedup vs baseline: 1.6415x; 1.2555x over previous
#include <cuda_runtime.h>
#include <cuda_fp16.h>
#include <cstdint>

#define BB 4
#define NSEQ 2048
#define CDIM 768
#define HNUM 12
#define DHEAD 64
#define QSE 0.18033688011112042f   // 0.125 * log2(e)

// ---------------- scratch ----------------
__device__ unsigned g_maskbits[NSEQ * (NSEQ / 32)];
__device__ int g_mask_mode;
__device__ __half g_xh[8192*768], g_xl[8192*768];
__device__ __half g_wqh[2304*768], g_wql[2304*768];
__device__ __half g_wph[768*768],  g_wpl[768*768];
__device__ __half g_Qh[48*2048*64], g_Ql[48*2048*64];   // [bh][tok][d], scaled
__device__ __half g_Kh[48*2048*64], g_Kl[48*2048*64];   // [bh][tok][d]
__device__ __half g_Vh[48*64*2048];                      // [bh][d][tok] (single-rounded)
__device__ __half g_Ch[8192*768],  g_Cl[8192*768];      // ctx hi/lo

// ---------------- helpers ----------------
__device__ __forceinline__ uint32_t smem_u32(const void* p){
    uint32_t a; asm("{ .reg .u64 t; cvta.to.shared.u64 t, %1; cvt.u32.u64 %0, t; }":"=r"(a):"l"(p)); return a;
}
__device__ __forceinline__ float ex2f(float x){ float r; asm("ex2.approx.f32 %0,%1;":"=f"(r):"f"(x)); return r; }
__device__ __forceinline__ uint32_t pk2(float a, float b){ __half2 h=__floats2half2_rn(a,b); return *(uint32_t*)&h; }

#define CPA16(dst, src) asm volatile("cp.async.cg.shared.global [%0], [%1], 16;\n"::"r"(dst),"l"(src):"memory")
#define CPA_COMMIT()    asm volatile("cp.async.commit_group;\n":::"memory")
#define CPA_WAIT0()     asm volatile("cp.async.wait_group 0;\n":::"memory")

#define LDSM4(r0,r1,r2,r3,ad) asm volatile("ldmatrix.sync.aligned.m8n8.x4.shared.b16 {%0,%1,%2,%3},[%4];":"=r"(r0),"=r"(r1),"=r"(r2),"=r"(r3):"r"(ad))
#define MMA(d,a,b) asm volatile("mma.sync.aligned.m16n8k16.row.col.f32.f16.f16.f32 {%0,%1,%2,%3},{%4,%5,%6,%7},{%8,%9},{%0,%1,%2,%3};" \
    :"+f"((d)[0]),"+f"((d)[1]),"+f"((d)[2]),"+f"((d)[3]) \
    :"r"((a)[0]),"r"((a)[1]),"r"((a)[2]),"r"((a)[3]),"r"((b)[0]),"r"((b)[1]))

__device__ __forceinline__ void ldA(uint32_t* a, uint32_t base, int rb, int kc, int P){
    int l = threadIdx.x & 31;
    uint32_t ad = base + (uint32_t)((rb + (l&7) + ((l>>3)&1)*8)*P + kc + (l>>4)*8)*2;
    LDSM4(a[0],a[1],a[2],a[3],ad);
}
__device__ __forceinline__ void ldB(uint32_t* b, uint32_t base, int nb, int kc, int P){
    int l = threadIdx.x & 31;
    uint32_t ad = base + (uint32_t)((nb + (l&7) + (l>>4)*8)*P + kc + ((l>>3)&1)*8)*2;
    LDSM4(b[0],b[1],b[2],b[3],ad);
}

// ---------------- mask probe + pack ----------------
__global__ void probe_mask(const unsigned* __restrict__ mw) {
    __shared__ int s_not01, s_notfloat;
    int tid = threadIdx.x;
    if (tid == 0) { s_not01 = 0; s_notfloat = 0; }
    __syncthreads();
    unsigned v = mw[tid];
    if (v != 0u && v != 1u) s_not01 = 1;
    if (v != 0u && v != 0x3F800000u) s_notfloat = 1;
    __syncthreads();
    if (tid == 0) g_mask_mode = (!s_not01) ? 0 : (!s_notfloat ? 1 : 2);
}
__global__ void mask_pack(const void* __restrict__ mask) {
    int gid = blockIdx.x * 256 + threadIdx.x;
    if (gid >= NSEQ * (NSEQ / 32)) return;
    long base = (long)(gid >> 6) * NSEQ + (long)(gid & 63) * 32;
    int mode = g_mask_mode;
    unsigned bits = 0u;
    if (mode == 0) {
        const int* p = (const int*)mask;
        #pragma unroll
        for (int j = 0; j < 32; j++) if (p[base + j] != 0) bits |= (1u << j);
    } else if (mode == 1) {
        const float* p = (const float*)mask;
        #pragma unroll
        for (int j = 0; j < 32; j++) if (p[base + j] != 0.0f) bits |= (1u << j);
    } else {
        const unsigned char* p = (const unsigned char*)mask;
        #pragma unroll
        for (int j = 0; j < 32; j++) if (p[base + j] != 0) bits |= (1u << j);
    }
    g_maskbits[gid] = bits;
}

// ---------------- split inputs ----------------
__global__ void splitx(const float* __restrict__ x){
    size_t i = ((size_t)blockIdx.x*256 + threadIdx.x)*4;
    float4 v = *(const float4*)(x + i);
    __half h0=__float2half_rn(v.x), h1=__float2half_rn(v.y), h2=__float2half_rn(v.z), h3=__float2half_rn(v.w);
    g_xh[i]=h0; g_xh[i+1]=h1; g_xh[i+2]=h2; g_xh[i+3]=h3;
    g_xl[i]  =__float2half_rn(v.x-__half2float(h0));
    g_xl[i+1]=__float2half_rn(v.y-__half2float(h1));
    g_xl[i+2]=__float2half_rn(v.z-__half2float(h2));
    g_xl[i+3]=__float2half_rn(v.w-__half2float(h3));
}
__global__ void wsplit(const float* __restrict__ W, int K, int N, int sel){
    __shared__ float t[32][33];
    __half* Wh = sel ? g_wph : g_wqh;
    __half* Wl = sel ? g_wpl : g_wql;
    int k0 = blockIdx.y*32, n0 = blockIdx.x*32;
    int tx = threadIdx.x, ty = threadIdx.y;
    #pragma unroll
    for (int i=0;i<4;i++) t[ty+i*8][tx] = W[(size_t)(k0+ty+i*8)*N + n0+tx];
    __syncthreads();
    #pragma unroll
    for (int i=0;i<4;i++){
        float v = t[tx][ty+i*8];
        __half h = __float2half_rn(v);
        size_t o = (size_t)(n0+ty+i*8)*K + k0+tx;
        Wh[o] = h; Wl[o] = __float2half_rn(v - __half2float(h));
    }
}

// ---------------- HMMA qkv GEMM: cp.async double-buffered ----------------
__global__ __launch_bounds__(256) void gemm_qkv(){
    __shared__ __half sm[2*9216];
    int tid = threadIdx.x, wid = tid>>5, lane = tid&31;
    int wm = wid>>1, wn = wid&1, gid = lane>>2, tig = lane&3;
    int m0 = blockIdx.y*128, n0 = blockIdx.x*64;
    uint32_t base = smem_u32(sm);
    float s[2][4][4];
    #pragma unroll
    for (int a=0;a<2;a++)
        #pragma unroll
        for (int b=0;b<4;b++)
            #pragma unroll
            for (int c=0;c<4;c++) s[a][b][c]=0.f;

    int arow = tid>>1, aseg = tid&1;
    const __half* pAh = g_xh + (size_t)(m0+arow)*768 + aseg*8;
    const __half* pAl = g_xl + (size_t)(m0+arow)*768 + aseg*8;
    int brow = (tid&127)>>1, bseg2 = tid&1;
    const __half* pB = (tid<128 ? g_wqh : g_wql) + (size_t)(n0+brow)*768 + bseg2*8;
    uint32_t dA  = base + (uint32_t)(arow*24 + aseg*8)*2;
    uint32_t dAl = dA + 6144;
    uint32_t dB  = base + 12288u + (tid<128?0u:3072u) + (uint32_t)(brow*24 + bseg2*8)*2;

    CPA16(dA, pAh); CPA16(dAl, pAl); CPA16(dB, pB);
    CPA_COMMIT();
    for (int k=0;k<48;k++){
        uint32_t bb = (uint32_t)(k&1)*18432u;
        CPA_WAIT0();
        __syncthreads();
        if (k<47){
            uint32_t nb = (uint32_t)((k+1)&1)*18432u;
            CPA16(dA+nb, pAh+(k+1)*16); CPA16(dAl+nb, pAl+(k+1)*16); CPA16(dB+nb, pB+(k+1)*16);
            CPA_COMMIT();
        }
        uint32_t ah[2][4], al[2][4], bh[8], bl[8];
        #pragma unroll
        for (int mt=0;mt<2;mt++){
            ldA(ah[mt], base+bb,      wm*32+mt*16, 0, 24);
            ldA(al[mt], base+bb+6144, wm*32+mt*16, 0, 24);
        }
        #pragma unroll
        for (int n2=0;n2<2;n2++){
            ldB(bh+n2*4, base+bb+12288, wn*32+n2*16, 0, 24);
            ldB(bl+n2*4, base+bb+15360, wn*32+n2*16, 0, 24);
        }
        #pragma unroll
        for (int mt=0;mt<2;mt++)
            #pragma unroll
            for (int nt=0;nt<4;nt++){
                MMA(s[mt][nt], ah[mt], bh+nt*2);
                MMA(s[mt][nt], al[mt], bh+nt*2);
                MMA(s[mt][nt], ah[mt], bl+nt*2);
            }
        __syncthreads();
    }
    int which = n0/768, rem = n0 - which*768;
    int bhq = (m0>>11)*HNUM + (rem>>6);
    int tok0 = m0 & 2047;
    #pragma unroll
    for (int mt=0;mt<2;mt++)
        #pragma unroll
        for (int nt=0;nt<4;nt++){
            int d0 = wn*32 + nt*8 + tig*2;
            if (which==2){
                #pragma unroll
                for (int c=0;c<4;c++){
                    int tok = tok0 + wm*32 + mt*16 + (c>>1)*8 + gid;
                    int d = d0 + (c&1);
                    g_Vh[((size_t)bhq*DHEAD + d)*NSEQ + tok] = __float2half_rn(s[mt][nt][c]);
                }
            } else {
                float sc = (which==0) ? QSE : 1.0f;
                __half* Ah = (which==0) ? g_Qh : g_Kh;
                __half* Al = (which==0) ? g_Ql : g_Kl;
                #pragma unroll
                for (int rh=0;rh<2;rh++){
                    int tok = tok0 + wm*32 + mt*16 + rh*8 + gid;
                    float v0 = s[mt][nt][rh*2+0]*sc, v1 = s[mt][nt][rh*2+1]*sc;
                    __half h0=__float2half_rn(v0), h1=__float2half_rn(v1);
                    size_t o = ((size_t)bhq*NSEQ + tok)*DHEAD + d0;
                    *(uint32_t*)(Ah+o) = pk2(v0,v1);
                    *(uint32_t*)(Al+o) = pk2(v0-__half2float(h0), v1-__half2float(h1));
                }
            }
        }
}

// ---------------- HMMA proj GEMM: cp.async double-buffered ----------------
__global__ __launch_bounds__(256) void gemm_proj(const float* __restrict__ bias,
                                                 float* __restrict__ Out){
    __shared__ __half sm[2*9216];
    int tid = threadIdx.x, wid = tid>>5, lane = tid&31;
    int wm = wid>>1, wn = wid&1, gid = lane>>2, tig = lane&3;
    int m0 = blockIdx.y*128, n0 = blockIdx.x*64;
    uint32_t base = smem_u32(sm);
    float s[2][4][4];
    #pragma unroll
    for (int a=0;a<2;a++)
        #pragma unroll
        for (int b=0;b<4;b++)
            #pragma unroll
            for (int c=0;c<4;c++) s[a][b][c]=0.f;

    int arow = tid>>1, aseg = tid&1;
    const __half* pAh = g_Ch + (size_t)(m0+arow)*768 + aseg*8;
    const __half* pAl = g_Cl + (size_t)(m0+arow)*768 + aseg*8;
    int brow = (tid&127)>>1, bseg2 = tid&1;
    const __half* pB = (tid<128 ? g_wph : g_wpl) + (size_t)(n0+brow)*768 + bseg2*8;
    uint32_t dA  = base + (uint32_t)(arow*24 + aseg*8)*2;
    uint32_t dAl = dA + 6144;
    uint32_t dB  = base + 12288u + (tid<128?0u:3072u) + (uint32_t)(brow*24 + bseg2*8)*2;

    CPA16(dA, pAh); CPA16(dAl, pAl); CPA16(dB, pB);
    CPA_COMMIT();
    for (int k=0;k<48;k++){
        uint32_t bb = (uint32_t)(k&1)*18432u;
        CPA_WAIT0();
        __syncthreads();
        if (k<47){
            uint32_t nb = (uint32_t)((k+1)&1)*18432u;
            CPA16(dA+nb, pAh+(k+1)*16); CPA16(dAl+nb, pAl+(k+1)*16); CPA16(dB+nb, pB+(k+1)*16);
            CPA_COMMIT();
        }
        uint32_t ah[2][4], al[2][4], bh[8], bl[8];
        #pragma unroll
        for (int mt=0;mt<2;mt++){
            ldA(ah[mt], base+bb,      wm*32+mt*16, 0, 24);
            ldA(al[mt], base+bb+6144, wm*32+mt*16, 0, 24);
        }
        #pragma unroll
        for (int n2=0;n2<2;n2++){
            ldB(bh+n2*4, base+bb+12288, wn*32+n2*16, 0, 24);
            ldB(bl+n2*4, base+bb+15360, wn*32+n2*16, 0, 24);
        }
        #pragma unroll
        for (int mt=0;mt<2;mt++)
            #pragma unroll
            for (int nt=0;nt<4;nt++){
                MMA(s[mt][nt], ah[mt], bh+nt*2);
                MMA(s[mt][nt], al[mt], bh+nt*2);
                MMA(s[mt][nt], ah[mt], bl+nt*2);
            }
        __syncthreads();
    }
    #pragma unroll
    for (int mt=0;mt<2;mt++)
        #pragma unroll
        for (int nt=0;nt<4;nt++)
            #pragma unroll
            for (int c=0;c<4;c++){
                int row = m0 + wm*32 + mt*16 + (c>>1)*8 + gid;
                int col = n0 + wn*32 + nt*8 + tig*2 + (c&1);
                Out[(size_t)row*768 + col] = s[mt][nt][c] + bias[col];
            }
}

// ---------------- HMMA attention: V single-rounded, 2 CTAs/SM -------------
// byte layout: Qh 0, Ql 18432, buf0 36864, buf1 64512 (each: Kh +0, Kl +9216,
// Vh +18432; 27648 B), P 92160. Total 110592 -> 2 CTAs/SM.
#define ATTN_SMEM (110592)
__global__ __launch_bounds__(256, 2) void attn_hm(){
    extern __shared__ __half sh[];
    uint32_t base = smem_u32(sh);
    int tid = threadIdx.x, wid = tid>>5, lane = tid&31;
    int wm = wid>>1, wn = wid&1, gid = lane>>2, tig = lane&3;
    int bh = blockIdx.y, b = bh/HNUM, hq = bh - b*HNUM;
    int row0 = blockIdx.x*128;

    // stage Q hi/lo via cp.async
    #pragma unroll
    for (int i=0;i<8;i++){
        int id = tid + i*256;
        int arr = id>>10, rem = id&1023, r = rem>>3, seg = rem&7;
        const __half* src = (arr ? g_Ql : g_Qh) + ((size_t)bh*NSEQ + row0 + r)*DHEAD + seg*8;
        CPA16(base + (uint32_t)(arr*18432 + r*144 + seg*16), src);
    }
    // stage KV tile 0 into buf0 (Kh, Kl, Vh)
    #pragma unroll
    for (int i=0;i<6;i++){
        int id = tid + i*256;
        int arr = id>>9, rem = id&511, r = rem>>3, seg = rem&7;
        const __half* src;
        if (arr==0)      src = g_Kh + ((size_t)bh*NSEQ + r)*DHEAD + seg*8;
        else if (arr==1) src = g_Kl + ((size_t)bh*NSEQ + r)*DHEAD + seg*8;
        else             src = g_Vh + ((size_t)bh*DHEAD + r)*NSEQ + seg*8;
        CPA16(base + (uint32_t)(36864 + arr*9216 + r*144 + seg*16), src);
    }
    CPA_COMMIT();

    float o[2][4][4], ls[2][2];
    #pragma unroll
    for (int mt=0;mt<2;mt++){ ls[mt][0]=0.f; ls[mt][1]=0.f;
        #pragma unroll
        for (int nt=0;nt<4;nt++)
            #pragma unroll
            for (int c=0;c<4;c++) o[mt][nt][c]=0.f; }
    const unsigned* mp[2][2];
    #pragma unroll
    for (int mt=0;mt<2;mt++)
        #pragma unroll
        for (int rh=0;rh<2;rh++)
            mp[mt][rh] = g_maskbits + (size_t)(row0 + wm*32 + mt*16 + rh*8 + gid)*64 + wn;

    CPA_WAIT0();
    __syncthreads();

    for (int t=0;t<32;t++){
        uint32_t cb = 36864u + (uint32_t)(t&1)*27648u;
        if (t<31){
            uint32_t nb = 36864u + (uint32_t)((t+1)&1)*27648u;
            #pragma unroll
            for (int i=0;i<6;i++){
                int id = tid + i*256;
                int arr = id>>9, rem = id&511, r = rem>>3, seg = rem&7;
                const __half* src;
                if (arr==0)      src = g_Kh + ((size_t)bh*NSEQ + (t+1)*64 + r)*DHEAD + seg*8;
                else if (arr==1) src = g_Kl + ((size_t)bh*NSEQ + (t+1)*64 + r)*DHEAD + seg*8;
                else             src = g_Vh + ((size_t)bh*DHEAD + r)*NSEQ + (t+1)*64 + seg*8;
                CPA16(base + nb + (uint32_t)(arr*9216 + r*144 + seg*16), src);
            }
            CPA_COMMIT();
        }
        // S = Q K^T (hh + lh + hl)
        float s[2][4][4];
        #pragma unroll
        for (int mt=0;mt<2;mt++)
            #pragma unroll
            for (int nt=0;nt<4;nt++)
                #pragma unroll
                for (int c=0;c<4;c++) s[mt][nt][c]=0.f;
        #pragma unroll
        for (int ks=0;ks<4;ks++){
            uint32_t qh[2][4], ql[2][4], kh[8], kl[8];
            #pragma unroll
            for (int mt=0;mt<2;mt++){
                ldA(qh[mt], base,       wm*32+mt*16, ks*16, 72);
                ldA(ql[mt], base+18432, wm*32+mt*16, ks*16, 72);
            }
            #pragma unroll
            for (int n2=0;n2<2;n2++){
                ldB(kh+n2*4, base+cb,      wn*32+n2*16, ks*16, 72);
                ldB(kl+n2*4, base+cb+9216, wn*32+n2*16, ks*16, 72);
            }
            #pragma unroll
            for (int mt=0;mt<2;mt++)
                #pragma unroll
                for (int nt=0;nt<4;nt++){
                    MMA(s[mt][nt], qh[mt], kh+nt*2);
                    MMA(s[mt][nt], ql[mt], kh+nt*2);
                    MMA(s[mt][nt], qh[mt], kl+nt*2);
                }
        }
        // mask + exp2 (clamped) + P to smem + partial row sums
        #pragma unroll
        for (int mt=0;mt<2;mt++){
            unsigned w0 = mp[mt][0][t*2];
            unsigned w1 = mp[mt][1][t*2];
            int r0 = wm*32 + mt*16 + gid;
            #pragma unroll
            for (int nt=0;nt<4;nt++){
                int bb = nt*8 + tig*2;
                float p0 = ((w0>>bb)&1u)     ? 0.f : ex2f(fminf(s[mt][nt][0],14.f));
                float p1 = ((w0>>(bb+1))&1u) ? 0.f : ex2f(fminf(s[mt][nt][1],14.f));
                float p2 = ((w1>>bb)&1u)     ? 0.f : ex2f(fminf(s[mt][nt][2],14.f));
                float p3 = ((w1>>(bb+1))&1u) ? 0.f : ex2f(fminf(s[mt][nt][3],14.f));
                ls[mt][0] += p0+p1; ls[mt][1] += p2+p3;
                int col = wn*32 + nt*8 + tig*2;
                *(uint32_t*)(sh + 46080 + r0*72 + col)     = pk2(p0,p1);
                *(uint32_t*)(sh + 46080 + (r0+8)*72 + col) = pk2(p2,p3);
            }
        }
        __syncthreads();
        // O += P V (P single-rounded, V single-rounded)
        #pragma unroll
        for (int ks=0;ks<4;ks++){
            uint32_t pa[2][4], vh[8];
            #pragma unroll
            for (int mt=0;mt<2;mt++)
                ldA(pa[mt], base+92160, wm*32+mt*16, ks*16, 72);
            #pragma unroll
            for (int n2=0;n2<2;n2++)
                ldB(vh+n2*4, base+cb+18432, wn*32+n2*16, ks*16, 72);
            #pragma unroll
            for (int mt=0;mt<2;mt++)
                #pragma unroll
                for (int nt=0;nt<4;nt++)
                    MMA(o[mt][nt], pa[mt], vh+nt*2);
        }
        if (t<31) CPA_WAIT0();
        __syncthreads();
    }
    // row sums: tig lanes then cross-wn via smem
    #pragma unroll
    for (int mt=0;mt<2;mt++)
        #pragma unroll
        for (int rh=0;rh<2;rh++){
            ls[mt][rh] += __shfl_xor_sync(0xffffffffu, ls[mt][rh], 1);
            ls[mt][rh] += __shfl_xor_sync(0xffffffffu, ls[mt][rh], 2);
        }
    float* lbuf = (float*)sh;
    if (tig==0){
        #pragma unroll
        for (int mt=0;mt<2;mt++)
            #pragma unroll
            for (int rh=0;rh<2;rh++)
                lbuf[wn*128 + wm*32 + mt*16 + rh*8 + gid] = ls[mt][rh];
    }
    __syncthreads();
    float inv[2][2];
    #pragma unroll
    for (int mt=0;mt<2;mt++)
        #pragma unroll
        for (int rh=0;rh<2;rh++){
            int r = wm*32 + mt*16 + rh*8 + gid;
            inv[mt][rh] = 1.0f / fmaxf(lbuf[r] + lbuf[128+r], 1e-30f);
        }
    #pragma unroll
    for (int mt=0;mt<2;mt++)
        #pragma unroll
        for (int nt=0;nt<4;nt++){
            int d0 = wn*32 + nt*8 + tig*2;
            #pragma unroll
            for (int rh=0;rh<2;rh++){
                float v0 = o[mt][nt][rh*2+0]*inv[mt][rh];
                float v1 = o[mt][nt][rh*2+1]*inv[mt][rh];
                int row = row0 + wm*32 + mt*16 + rh*8 + gid;
                size_t off = ((size_t)b*NSEQ + row)*CDIM + hq*64 + d0;
                __half h0 = __float2half_rn(v0), h1 = __float2half_rn(v1);
                *(uint32_t*)(g_Ch+off) = pk2(v0,v1);
                *(uint32_t*)(g_Cl+off) = pk2(v0-__half2float(h0), v1-__half2float(h1));
            }
        }
}

// ---------------- launch ----------------
extern "C" void kernel_launch(void* const* d_in, const int* in_sizes, int n_in,
                              void* d_out, int out_size){
    const float* x      = (const float*)d_in[0];
    const void*  mask   = d_in[1];
    const float* w_qkv  = (const float*)d_in[2];
    const float* w_proj = (const float*)d_in[3];
    const float* b_proj = (const float*)d_in[4];
    float* out = (float*)d_out;

    cudaFuncSetAttribute(attn_hm, cudaFuncAttributeMaxDynamicSharedMemorySize, ATTN_SMEM);

    probe_mask<<<1, 256>>>((const unsigned*)mask);
    mask_pack<<<512, 256>>>(mask);
    splitx<<<6144, 256>>>(x);
    wsplit<<<dim3(72,24), dim3(32,8)>>>(w_qkv, 768, 2304, 0);
    wsplit<<<dim3(24,24), dim3(32,8)>>>(w_proj, 768, 768, 1);
    gemm_qkv<<<dim3(36,64), 256>>>();
    attn_hm<<<dim3(16,48), 256, ATTN_SMEM>>>();
    gemm_proj<<<dim3(12,64), 256>>>(b_proj, out);
}

// round 13
// speedup vs baseline: 1.7945x; 1.0932x over previous
#include <cuda_runtime.h>
#include <cuda_fp16.h>
#include <cstdint>

#define BB 4
#define NSEQ 2048
#define CDIM 768
#define HNUM 12
#define DHEAD 64
#define QSE 0.18033688011112042f   // 0.125 * log2(e)

// ---------------- scratch ----------------
__device__ unsigned g_maskbits[NSEQ * (NSEQ / 32)];
__device__ int g_mask_mode;
__device__ __half g_xh[8192*768], g_xl[8192*768];
__device__ __half g_wqh[2304*768], g_wql[2304*768];
__device__ __half g_wph[768*768],  g_wpl[768*768];
__device__ __half g_Qh[48*2048*64];                     // [bh][tok][d], scaled, fp16
__device__ __half g_Kh[48*2048*64];                     // [bh][tok][d], fp16
__device__ __half g_Vh[48*64*2048];                     // [bh][d][tok], fp16
__device__ __half g_Ch[8192*768],  g_Cl[8192*768];      // ctx hi/lo (proj needs split)

// ---------------- helpers ----------------
__device__ __forceinline__ uint32_t smem_u32(const void* p){
    uint32_t a; asm("{ .reg .u64 t; cvta.to.shared.u64 t, %1; cvt.u32.u64 %0, t; }":"=r"(a):"l"(p)); return a;
}
__device__ __forceinline__ float ex2f(float x){ float r; asm("ex2.approx.f32 %0,%1;":"=f"(r):"f"(x)); return r; }
__device__ __forceinline__ uint32_t pk2(float a, float b){ __half2 h=__floats2half2_rn(a,b); return *(uint32_t*)&h; }

#define CPA16(dst, src) asm volatile("cp.async.cg.shared.global [%0], [%1], 16;\n"::"r"(dst),"l"(src):"memory")
#define CPA_COMMIT()    asm volatile("cp.async.commit_group;\n":::"memory")
#define CPA_WAIT0()     asm volatile("cp.async.wait_group 0;\n":::"memory")

#define LDSM4(r0,r1,r2,r3,ad) asm volatile("ldmatrix.sync.aligned.m8n8.x4.shared.b16 {%0,%1,%2,%3},[%4];":"=r"(r0),"=r"(r1),"=r"(r2),"=r"(r3):"r"(ad))
#define MMA(d,a,b) asm volatile("mma.sync.aligned.m16n8k16.row.col.f32.f16.f16.f32 {%0,%1,%2,%3},{%4,%5,%6,%7},{%8,%9},{%0,%1,%2,%3};" \
    :"+f"((d)[0]),"+f"((d)[1]),"+f"((d)[2]),"+f"((d)[3]) \
    :"r"((a)[0]),"r"((a)[1]),"r"((a)[2]),"r"((a)[3]),"r"((b)[0]),"r"((b)[1]))

__device__ __forceinline__ void ldA(uint32_t* a, uint32_t base, int rb, int kc, int P){
    int l = threadIdx.x & 31;
    uint32_t ad = base + (uint32_t)((rb + (l&7) + ((l>>3)&1)*8)*P + kc + (l>>4)*8)*2;
    LDSM4(a[0],a[1],a[2],a[3],ad);
}
__device__ __forceinline__ void ldB(uint32_t* b, uint32_t base, int nb, int kc, int P){
    int l = threadIdx.x & 31;
    uint32_t ad = base + (uint32_t)((nb + (l&7) + (l>>4)*8)*P + kc + ((l>>3)&1)*8)*2;
    LDSM4(b[0],b[1],b[2],b[3],ad);
}

// ---------------- mask probe + pack ----------------
__global__ void probe_mask(const unsigned* __restrict__ mw) {
    __shared__ int s_not01, s_notfloat;
    int tid = threadIdx.x;
    if (tid == 0) { s_not01 = 0; s_notfloat = 0; }
    __syncthreads();
    unsigned v = mw[tid];
    if (v != 0u && v != 1u) s_not01 = 1;
    if (v != 0u && v != 0x3F800000u) s_notfloat = 1;
    __syncthreads();
    if (tid == 0) g_mask_mode = (!s_not01) ? 0 : (!s_notfloat ? 1 : 2);
}
__global__ void mask_pack(const void* __restrict__ mask) {
    int gid = blockIdx.x * 256 + threadIdx.x;
    if (gid >= NSEQ * (NSEQ / 32)) return;
    long base = (long)(gid >> 6) * NSEQ + (long)(gid & 63) * 32;
    int mode = g_mask_mode;
    unsigned bits = 0u;
    if (mode == 0) {
        const int* p = (const int*)mask;
        #pragma unroll
        for (int j = 0; j < 32; j++) if (p[base + j] != 0) bits |= (1u << j);
    } else if (mode == 1) {
        const float* p = (const float*)mask;
        #pragma unroll
        for (int j = 0; j < 32; j++) if (p[base + j] != 0.0f) bits |= (1u << j);
    } else {
        const unsigned char* p = (const unsigned char*)mask;
        #pragma unroll
        for (int j = 0; j < 32; j++) if (p[base + j] != 0) bits |= (1u << j);
    }
    g_maskbits[gid] = bits;
}

// ---------------- split inputs ----------------
__global__ void splitx(const float* __restrict__ x){
    size_t i = ((size_t)blockIdx.x*256 + threadIdx.x)*4;
    float4 v = *(const float4*)(x + i);
    __half h0=__float2half_rn(v.x), h1=__float2half_rn(v.y), h2=__float2half_rn(v.z), h3=__float2half_rn(v.w);
    g_xh[i]=h0; g_xh[i+1]=h1; g_xh[i+2]=h2; g_xh[i+3]=h3;
    g_xl[i]  =__float2half_rn(v.x-__half2float(h0));
    g_xl[i+1]=__float2half_rn(v.y-__half2float(h1));
    g_xl[i+2]=__float2half_rn(v.z-__half2float(h2));
    g_xl[i+3]=__float2half_rn(v.w-__half2float(h3));
}
__global__ void wsplit(const float* __restrict__ W, int K, int N, int sel){
    __shared__ float t[32][33];
    __half* Wh = sel ? g_wph : g_wqh;
    __half* Wl = sel ? g_wpl : g_wql;
    int k0 = blockIdx.y*32, n0 = blockIdx.x*32;
    int tx = threadIdx.x, ty = threadIdx.y;
    #pragma unroll
    for (int i=0;i<4;i++) t[ty+i*8][tx] = W[(size_t)(k0+ty+i*8)*N + n0+tx];
    __syncthreads();
    #pragma unroll
    for (int i=0;i<4;i++){
        float v = t[tx][ty+i*8];
        __half h = __float2half_rn(v);
        size_t o = (size_t)(n0+ty+i*8)*K + k0+tx;
        Wh[o] = h; Wl[o] = __float2half_rn(v - __half2float(h));
    }
}

// ---------------- HMMA qkv GEMM: cp.async double-buffered ----------------
__global__ __launch_bounds__(256) void gemm_qkv(){
    __shared__ __half sm[2*9216];
    int tid = threadIdx.x, wid = tid>>5, lane = tid&31;
    int wm = wid>>1, wn = wid&1, gid = lane>>2, tig = lane&3;
    int m0 = blockIdx.y*128, n0 = blockIdx.x*64;
    uint32_t base = smem_u32(sm);
    float s[2][4][4];
    #pragma unroll
    for (int a=0;a<2;a++)
        #pragma unroll
        for (int b=0;b<4;b++)
            #pragma unroll
            for (int c=0;c<4;c++) s[a][b][c]=0.f;

    int arow = tid>>1, aseg = tid&1;
    const __half* pAh = g_xh + (size_t)(m0+arow)*768 + aseg*8;
    const __half* pAl = g_xl + (size_t)(m0+arow)*768 + aseg*8;
    int brow = (tid&127)>>1, bseg2 = tid&1;
    const __half* pB = (tid<128 ? g_wqh : g_wql) + (size_t)(n0+brow)*768 + bseg2*8;
    uint32_t dA  = base + (uint32_t)(arow*24 + aseg*8)*2;
    uint32_t dAl = dA + 6144;
    uint32_t dB  = base + 12288u + (tid<128?0u:3072u) + (uint32_t)(brow*24 + bseg2*8)*2;

    CPA16(dA, pAh); CPA16(dAl, pAl); CPA16(dB, pB);
    CPA_COMMIT();
    for (int k=0;k<48;k++){
        uint32_t bb = (uint32_t)(k&1)*18432u;
        CPA_WAIT0();
        __syncthreads();
        if (k<47){
            uint32_t nb = (uint32_t)((k+1)&1)*18432u;
            CPA16(dA+nb, pAh+(k+1)*16); CPA16(dAl+nb, pAl+(k+1)*16); CPA16(dB+nb, pB+(k+1)*16);
            CPA_COMMIT();
        }
        uint32_t ah[2][4], al[2][4], bh[8], bl[8];
        #pragma unroll
        for (int mt=0;mt<2;mt++){
            ldA(ah[mt], base+bb,      wm*32+mt*16, 0, 24);
            ldA(al[mt], base+bb+6144, wm*32+mt*16, 0, 24);
        }
        #pragma unroll
        for (int n2=0;n2<2;n2++){
            ldB(bh+n2*4, base+bb+12288, wn*32+n2*16, 0, 24);
            ldB(bl+n2*4, base+bb+15360, wn*32+n2*16, 0, 24);
        }
        #pragma unroll
        for (int mt=0;mt<2;mt++)
            #pragma unroll
            for (int nt=0;nt<4;nt++){
                MMA(s[mt][nt], ah[mt], bh+nt*2);
                MMA(s[mt][nt], al[mt], bh+nt*2);
                MMA(s[mt][nt], ah[mt], bl+nt*2);
            }
        __syncthreads();
    }
    int which = n0/768, rem = n0 - which*768;
    int bhq = (m0>>11)*HNUM + (rem>>6);
    int tok0 = m0 & 2047;
    #pragma unroll
    for (int mt=0;mt<2;mt++)
        #pragma unroll
        for (int nt=0;nt<4;nt++){
            int d0 = wn*32 + nt*8 + tig*2;
            if (which==2){
                #pragma unroll
                for (int c=0;c<4;c++){
                    int tok = tok0 + wm*32 + mt*16 + (c>>1)*8 + gid;
                    int d = d0 + (c&1);
                    g_Vh[((size_t)bhq*DHEAD + d)*NSEQ + tok] = __float2half_rn(s[mt][nt][c]);
                }
            } else {
                float sc = (which==0) ? QSE : 1.0f;
                __half* Ah = (which==0) ? g_Qh : g_Kh;
                #pragma unroll
                for (int rh=0;rh<2;rh++){
                    int tok = tok0 + wm*32 + mt*16 + rh*8 + gid;
                    size_t o = ((size_t)bhq*NSEQ + tok)*DHEAD + d0;
                    *(uint32_t*)(Ah+o) = pk2(s[mt][nt][rh*2+0]*sc, s[mt][nt][rh*2+1]*sc);
                }
            }
        }
}

// ---------------- HMMA proj GEMM: cp.async double-buffered ----------------
__global__ __launch_bounds__(256) void gemm_proj(const float* __restrict__ bias,
                                                 float* __restrict__ Out){
    __shared__ __half sm[2*9216];
    int tid = threadIdx.x, wid = tid>>5, lane = tid&31;
    int wm = wid>>1, wn = wid&1, gid = lane>>2, tig = lane&3;
    int m0 = blockIdx.y*128, n0 = blockIdx.x*64;
    uint32_t base = smem_u32(sm);
    float s[2][4][4];
    #pragma unroll
    for (int a=0;a<2;a++)
        #pragma unroll
        for (int b=0;b<4;b++)
            #pragma unroll
            for (int c=0;c<4;c++) s[a][b][c]=0.f;

    int arow = tid>>1, aseg = tid&1;
    const __half* pAh = g_Ch + (size_t)(m0+arow)*768 + aseg*8;
    const __half* pAl = g_Cl + (size_t)(m0+arow)*768 + aseg*8;
    int brow = (tid&127)>>1, bseg2 = tid&1;
    const __half* pB = (tid<128 ? g_wph : g_wpl) + (size_t)(n0+brow)*768 + bseg2*8;
    uint32_t dA  = base + (uint32_t)(arow*24 + aseg*8)*2;
    uint32_t dAl = dA + 6144;
    uint32_t dB  = base + 12288u + (tid<128?0u:3072u) + (uint32_t)(brow*24 + bseg2*8)*2;

    CPA16(dA, pAh); CPA16(dAl, pAl); CPA16(dB, pB);
    CPA_COMMIT();
    for (int k=0;k<48;k++){
        uint32_t bb = (uint32_t)(k&1)*18432u;
        CPA_WAIT0();
        __syncthreads();
        if (k<47){
            uint32_t nb = (uint32_t)((k+1)&1)*18432u;
            CPA16(dA+nb, pAh+(k+1)*16); CPA16(dAl+nb, pAl+(k+1)*16); CPA16(dB+nb, pB+(k+1)*16);
            CPA_COMMIT();
        }
        uint32_t ah[2][4], al[2][4], bh[8], bl[8];
        #pragma unroll
        for (int mt=0;mt<2;mt++){
            ldA(ah[mt], base+bb,      wm*32+mt*16, 0, 24);
            ldA(al[mt], base+bb+6144, wm*32+mt*16, 0, 24);
        }
        #pragma unroll
        for (int n2=0;n2<2;n2++){
            ldB(bh+n2*4, base+bb+12288, wn*32+n2*16, 0, 24);
            ldB(bl+n2*4, base+bb+15360, wn*32+n2*16, 0, 24);
        }
        #pragma unroll
        for (int mt=0;mt<2;mt++)
            #pragma unroll
            for (int nt=0;nt<4;nt++){
                MMA(s[mt][nt], ah[mt], bh+nt*2);
                MMA(s[mt][nt], al[mt], bh+nt*2);
                MMA(s[mt][nt], ah[mt], bl+nt*2);
            }
        __syncthreads();
    }
    #pragma unroll
    for (int mt=0;mt<2;mt++)
        #pragma unroll
        for (int nt=0;nt<4;nt++)
            #pragma unroll
            for (int c=0;c<4;c++){
                int row = m0 + wm*32 + mt*16 + (c>>1)*8 + gid;
                int col = n0 + wn*32 + nt*8 + tig*2 + (c&1);
                Out[(size_t)row*768 + col] = s[mt][nt][c] + bias[col];
            }
}

// ---------------- HMMA attention: fp16 QK + fp16 V, 3 CTAs/SM -------------
// byte layout: Qh 0 (18432), P 18432 (18432), buf0 36864, buf1 55296
//   each buf: Kh +0 (9216), Vh +9216 (9216). Total 73728 -> 3 CTAs/SM.
#define ATTN_SMEM (73728)
__global__ __launch_bounds__(256, 3) void attn_hm(){
    extern __shared__ __half sh[];
    uint32_t base = smem_u32(sh);
    int tid = threadIdx.x, wid = tid>>5, lane = tid&31;
    int wm = wid>>1, wn = wid&1, gid = lane>>2, tig = lane&3;
    int bh = blockIdx.y, b = bh/HNUM, hq = bh - b*HNUM;
    int row0 = blockIdx.x*128;

    // stage Q via cp.async
    #pragma unroll
    for (int i=0;i<4;i++){
        int id = tid + i*256;
        int r = id>>3, seg = id&7;
        const __half* src = g_Qh + ((size_t)bh*NSEQ + row0 + r)*DHEAD + seg*8;
        CPA16(base + (uint32_t)(r*144 + seg*16), src);
    }
    // stage KV tile 0 into buf0 (Kh, Vh)
    #pragma unroll
    for (int i=0;i<4;i++){
        int id = tid + i*256;
        int arr = id>>9, rem = id&511, r = rem>>3, seg = rem&7;
        const __half* src = arr ? g_Vh + ((size_t)bh*DHEAD + r)*NSEQ + seg*8
                                : g_Kh + ((size_t)bh*NSEQ + r)*DHEAD + seg*8;
        CPA16(base + (uint32_t)(36864 + arr*9216 + r*144 + seg*16), src);
    }
    CPA_COMMIT();

    float o[2][4][4], ls[2][2];
    #pragma unroll
    for (int mt=0;mt<2;mt++){ ls[mt][0]=0.f; ls[mt][1]=0.f;
        #pragma unroll
        for (int nt=0;nt<4;nt++)
            #pragma unroll
            for (int c=0;c<4;c++) o[mt][nt][c]=0.f; }
    const unsigned* mp[2][2];
    #pragma unroll
    for (int mt=0;mt<2;mt++)
        #pragma unroll
        for (int rh=0;rh<2;rh++)
            mp[mt][rh] = g_maskbits + (size_t)(row0 + wm*32 + mt*16 + rh*8 + gid)*64 + wn;

    CPA_WAIT0();
    __syncthreads();

    for (int t=0;t<32;t++){
        uint32_t cb = 36864u + (uint32_t)(t&1)*18432u;
        if (t<31){
            uint32_t nb = 36864u + (uint32_t)((t+1)&1)*18432u;
            #pragma unroll
            for (int i=0;i<4;i++){
                int id = tid + i*256;
                int arr = id>>9, rem = id&511, r = rem>>3, seg = rem&7;
                const __half* src = arr ? g_Vh + ((size_t)bh*DHEAD + r)*NSEQ + (t+1)*64 + seg*8
                                        : g_Kh + ((size_t)bh*NSEQ + (t+1)*64 + r)*DHEAD + seg*8;
                CPA16(base + nb + (uint32_t)(arr*9216 + r*144 + seg*16), src);
            }
            CPA_COMMIT();
        }
        // S = Q K^T (pure fp16)
        float s[2][4][4];
        #pragma unroll
        for (int mt=0;mt<2;mt++)
            #pragma unroll
            for (int nt=0;nt<4;nt++)
                #pragma unroll
                for (int c=0;c<4;c++) s[mt][nt][c]=0.f;
        #pragma unroll
        for (int ks=0;ks<4;ks++){
            uint32_t qh[2][4], kh[8];
            #pragma unroll
            for (int mt=0;mt<2;mt++)
                ldA(qh[mt], base, wm*32+mt*16, ks*16, 72);
            #pragma unroll
            for (int n2=0;n2<2;n2++)
                ldB(kh+n2*4, base+cb, wn*32+n2*16, ks*16, 72);
            #pragma unroll
            for (int mt=0;mt<2;mt++)
                #pragma unroll
                for (int nt=0;nt<4;nt++)
                    MMA(s[mt][nt], qh[mt], kh+nt*2);
        }
        // mask + exp2 (clamped) + P to smem + partial row sums
        #pragma unroll
        for (int mt=0;mt<2;mt++){
            unsigned w0 = mp[mt][0][t*2];
            unsigned w1 = mp[mt][1][t*2];
            int r0 = wm*32 + mt*16 + gid;
            #pragma unroll
            for (int nt=0;nt<4;nt++){
                int bb = nt*8 + tig*2;
                float p0 = ((w0>>bb)&1u)     ? 0.f : ex2f(fminf(s[mt][nt][0],14.f));
                float p1 = ((w0>>(bb+1))&1u) ? 0.f : ex2f(fminf(s[mt][nt][1],14.f));
                float p2 = ((w1>>bb)&1u)     ? 0.f : ex2f(fminf(s[mt][nt][2],14.f));
                float p3 = ((w1>>(bb+1))&1u) ? 0.f : ex2f(fminf(s[mt][nt][3],14.f));
                ls[mt][0] += p0+p1; ls[mt][1] += p2+p3;
                int col = wn*32 + nt*8 + tig*2;
                *(uint32_t*)(sh + 9216 + r0*72 + col)     = pk2(p0,p1);
                *(uint32_t*)(sh + 9216 + (r0+8)*72 + col) = pk2(p2,p3);
            }
        }
        __syncthreads();
        // O += P V
        #pragma unroll
        for (int ks=0;ks<4;ks++){
            uint32_t pa[2][4], vh[8];
            #pragma unroll
            for (int mt=0;mt<2;mt++)
                ldA(pa[mt], base+18432, wm*32+mt*16, ks*16, 72);
            #pragma unroll
            for (int n2=0;n2<2;n2++)
                ldB(vh+n2*4, base+cb+9216, wn*32+n2*16, ks*16, 72);
            #pragma unroll
            for (int mt=0;mt<2;mt++)
                #pragma unroll
                for (int nt=0;nt<4;nt++)
                    MMA(o[mt][nt], pa[mt], vh+nt*2);
        }
        if (t<31) CPA_WAIT0();
        __syncthreads();
    }
    // row sums: tig lanes then cross-wn via smem
    #pragma unroll
    for (int mt=0;mt<2;mt++)
        #pragma unroll
        for (int rh=0;rh<2;rh++){
            ls[mt][rh] += __shfl_xor_sync(0xffffffffu, ls[mt][rh], 1);
            ls[mt][rh] += __shfl_xor_sync(0xffffffffu, ls[mt][rh], 2);
        }
    float* lbuf = (float*)sh;
    if (tig==0){
        #pragma unroll
        for (int mt=0;mt<2;mt++)
            #pragma unroll
            for (int rh=0;rh<2;rh++)
                lbuf[wn*128 + wm*32 + mt*16 + rh*8 + gid] = ls[mt][rh];
    }
    __syncthreads();
    float inv[2][2];
    #pragma unroll
    for (int mt=0;mt<2;mt++)
        #pragma unroll
        for (int rh=0;rh<2;rh++){
            int r = wm*32 + mt*16 + rh*8 + gid;
            inv[mt][rh] = 1.0f / fmaxf(lbuf[r] + lbuf[128+r], 1e-30f);
        }
    #pragma unroll
    for (int mt=0;mt<2;mt++)
        #pragma unroll
        for (int nt=0;nt<4;nt++){
            int d0 = wn*32 + nt*8 + tig*2;
            #pragma unroll
            for (int rh=0;rh<2;rh++){
                float v0 = o[mt][nt][rh*2+0]*inv[mt][rh];
                float v1 = o[mt][nt][rh*2+1]*inv[mt][rh];
                int row = row0 + wm*32 + mt*16 + rh*8 + gid;
                size_t off = ((size_t)b*NSEQ + row)*CDIM + hq*64 + d0;
                __half h0 = __float2half_rn(v0), h1 = __float2half_rn(v1);
                *(uint32_t*)(g_Ch+off) = pk2(v0,v1);
                *(uint32_t*)(g_Cl+off) = pk2(v0-__half2float(h0), v1-__half2float(h1));
            }
        }
}

// ---------------- launch ----------------
extern "C" void kernel_launch(void* const* d_in, const int* in_sizes, int n_in,
                              void* d_out, int out_size){
    const float* x      = (const float*)d_in[0];
    const void*  mask   = d_in[1];
    const float* w_qkv  = (const float*)d_in[2];
    const float* w_proj = (const float*)d_in[3];
    const float* b_proj = (const float*)d_in[4];
    float* out = (float*)d_out;

    cudaFuncSetAttribute(attn_hm, cudaFuncAttributeMaxDynamicSharedMemorySize, ATTN_SMEM);

    probe_mask<<<1, 256>>>((const unsigned*)mask);
    mask_pack<<<512, 256>>>(mask);
    splitx<<<6144, 256>>>(x);
    wsplit<<<dim3(72,24), dim3(32,8)>>>(w_qkv, 768, 2304, 0);
    wsplit<<<dim3(24,24), dim3(32,8)>>>(w_proj, 768, 768, 1);
    gemm_qkv<<<dim3(36,64), 256>>>();
    attn_hm<<<dim3(16,48), 256, ATTN_SMEM>>>();
    gemm_proj<<<dim3(12,64), 256>>>(b_proj, out);
}

// round 14
// speedup vs baseline: 2.1748x; 1.2119x over previous
#include <cuda_runtime.h>
#include <cuda_fp16.h>
#include <cstdint>

#define BB 4
#define NSEQ 2048
#define CDIM 768
#define HNUM 12
#define DHEAD 64
#define QSE 0.18033688011112042f   // 0.125 * log2(e)

// ---------------- scratch ----------------
__device__ unsigned g_maskbits[NSEQ * (NSEQ / 32)];
__device__ int g_mask_mode;
__device__ __half g_xh[8192*768];
__device__ __half g_wqh[2304*768], g_wql[2304*768];
__device__ __half g_wph[768*768],  g_wpl[768*768];
__device__ __half g_Qh[48*2048*64];                     // [bh][tok][d], scaled, fp16
__device__ __half g_Kh[48*2048*64];                     // [bh][tok][d], fp16
__device__ __half g_Vh[48*64*2048];                     // [bh][d][tok], fp16
__device__ __half g_Ch[8192*768],  g_Cl[8192*768];      // ctx hi/lo

// ---------------- helpers ----------------
__device__ __forceinline__ uint32_t smem_u32(const void* p){
    uint32_t a; asm("{ .reg .u64 t; cvta.to.shared.u64 t, %1; cvt.u32.u64 %0, t; }":"=r"(a):"l"(p)); return a;
}
__device__ __forceinline__ float ex2f(float x){ float r; asm("ex2.approx.f32 %0,%1;":"=f"(r):"f"(x)); return r; }
__device__ __forceinline__ uint32_t pk2(float a, float b){ __half2 h=__floats2half2_rn(a,b); return *(uint32_t*)&h; }

#define CPA16(dst, src) asm volatile("cp.async.cg.shared.global [%0], [%1], 16;\n"::"r"(dst),"l"(src):"memory")
#define CPA_COMMIT()    asm volatile("cp.async.commit_group;\n":::"memory")
#define CPA_WAIT0()     asm volatile("cp.async.wait_group 0;\n":::"memory")

#define LDSM4(r0,r1,r2,r3,ad) asm volatile("ldmatrix.sync.aligned.m8n8.x4.shared.b16 {%0,%1,%2,%3},[%4];":"=r"(r0),"=r"(r1),"=r"(r2),"=r"(r3):"r"(ad))
#define MMA(d,a,b) asm volatile("mma.sync.aligned.m16n8k16.row.col.f32.f16.f16.f32 {%0,%1,%2,%3},{%4,%5,%6,%7},{%8,%9},{%0,%1,%2,%3};" \
    :"+f"((d)[0]),"+f"((d)[1]),"+f"((d)[2]),"+f"((d)[3]) \
    :"r"((a)[0]),"r"((a)[1]),"r"((a)[2]),"r"((a)[3]),"r"((b)[0]),"r"((b)[1]))

__device__ __forceinline__ void ldA(uint32_t* a, uint32_t base, int rb, int kc, int P){
    int l = threadIdx.x & 31;
    uint32_t ad = base + (uint32_t)((rb + (l&7) + ((l>>3)&1)*8)*P + kc + (l>>4)*8)*2;
    LDSM4(a[0],a[1],a[2],a[3],ad);
}
__device__ __forceinline__ void ldB(uint32_t* b, uint32_t base, int nb, int kc, int P){
    int l = threadIdx.x & 31;
    uint32_t ad = base + (uint32_t)((nb + (l&7) + (l>>4)*8)*P + kc + ((l>>3)&1)*8)*2;
    LDSM4(b[0],b[1],b[2],b[3],ad);
}

// ---------------- mask probe + pack ----------------
__global__ void probe_mask(const unsigned* __restrict__ mw) {
    __shared__ int s_not01, s_notfloat;
    int tid = threadIdx.x;
    if (tid == 0) { s_not01 = 0; s_notfloat = 0; }
    __syncthreads();
    unsigned v = mw[tid];
    if (v != 0u && v != 1u) s_not01 = 1;
    if (v != 0u && v != 0x3F800000u) s_notfloat = 1;
    __syncthreads();
    if (tid == 0) g_mask_mode = (!s_not01) ? 0 : (!s_notfloat ? 1 : 2);
}
__global__ void mask_pack(const void* __restrict__ mask) {
    int gid = blockIdx.x * 256 + threadIdx.x;
    if (gid >= NSEQ * (NSEQ / 32)) return;
    long base = (long)(gid >> 6) * NSEQ + (long)(gid & 63) * 32;
    int mode = g_mask_mode;
    unsigned bits = 0u;
    if (mode == 0) {
        const int* p = (const int*)mask;
        #pragma unroll
        for (int j = 0; j < 32; j++) if (p[base + j] != 0) bits |= (1u << j);
    } else if (mode == 1) {
        const float* p = (const float*)mask;
        #pragma unroll
        for (int j = 0; j < 32; j++) if (p[base + j] != 0.0f) bits |= (1u << j);
    } else {
        const unsigned char* p = (const unsigned char*)mask;
        #pragma unroll
        for (int j = 0; j < 32; j++) if (p[base + j] != 0) bits |= (1u << j);
    }
    g_maskbits[gid] = bits;
}

// ---------------- round x to fp16 ----------------
__global__ void splitx(const float* __restrict__ x){
    size_t i = ((size_t)blockIdx.x*256 + threadIdx.x)*4;
    float4 v = *(const float4*)(x + i);
    uint2 hv; hv.x = pk2(v.x, v.y); hv.y = pk2(v.z, v.w);
    *(uint2*)(g_xh + i) = hv;
}
__global__ void wsplit(const float* __restrict__ W, int K, int N, int sel){
    __shared__ float t[32][33];
    __half* Wh = sel ? g_wph : g_wqh;
    __half* Wl = sel ? g_wpl : g_wql;
    int k0 = blockIdx.y*32, n0 = blockIdx.x*32;
    int tx = threadIdx.x, ty = threadIdx.y;
    #pragma unroll
    for (int i=0;i<4;i++) t[ty+i*8][tx] = W[(size_t)(k0+ty+i*8)*N + n0+tx];
    __syncthreads();
    #pragma unroll
    for (int i=0;i<4;i++){
        float v = t[tx][ty+i*8];
        __half h = __float2half_rn(v);
        size_t o = (size_t)(n0+ty+i*8)*K + k0+tx;
        Wh[o] = h; Wl[o] = __float2half_rn(v - __half2float(h));
    }
}

// ---------------- HMMA qkv GEMM: 2-pass, k-chunk 32, double-buffered -------
// per buf (bytes): Ah 0 (10240), Bh 10240 (5120), Bl 15360 (5120) = 20480
__global__ __launch_bounds__(256) void gemm_qkv(){
    __shared__ __half sm[20480];
    int tid = threadIdx.x, wid = tid>>5, lane = tid&31;
    int wm = wid>>1, wn = wid&1, gid = lane>>2, tig = lane&3;
    int m0 = blockIdx.y*128, n0 = blockIdx.x*64;
    uint32_t base = smem_u32(sm);
    float s[2][4][4];
    #pragma unroll
    for (int a=0;a<2;a++)
        #pragma unroll
        for (int b=0;b<4;b++)
            #pragma unroll
            for (int c=0;c<4;c++) s[a][b][c]=0.f;

    // prologue: stage chunk 0
    #pragma unroll
    for (int i=0;i<2;i++){
        int id = tid + i*256;
        int r = id>>2, seg = id&3;
        CPA16(base + (uint32_t)(r*80 + seg*16), g_xh + (size_t)(m0+r)*768 + seg*8);
    }
    #pragma unroll
    for (int i=0;i<2;i++){
        int id = tid + i*256;
        int arr = id>>8, rem = id&255, r = rem>>2, seg = rem&3;
        CPA16(base + (uint32_t)(10240 + arr*5120 + r*80 + seg*16),
              (arr ? g_wql : g_wqh) + (size_t)(n0+r)*768 + seg*8);
    }
    CPA_COMMIT();

    for (int k=0;k<24;k++){
        uint32_t bb = (uint32_t)(k&1)*20480u;
        CPA_WAIT0();
        __syncthreads();
        if (k<23){
            uint32_t nb = (uint32_t)((k+1)&1)*20480u;
            int k0 = (k+1)*32;
            #pragma unroll
            for (int i=0;i<2;i++){
                int id = tid + i*256;
                int r = id>>2, seg = id&3;
                CPA16(base + nb + (uint32_t)(r*80 + seg*16),
                      g_xh + (size_t)(m0+r)*768 + k0 + seg*8);
            }
            #pragma unroll
            for (int i=0;i<2;i++){
                int id = tid + i*256;
                int arr = id>>8, rem = id&255, r = rem>>2, seg = rem&3;
                CPA16(base + nb + (uint32_t)(10240 + arr*5120 + r*80 + seg*16),
                      (arr ? g_wql : g_wqh) + (size_t)(n0+r)*768 + k0 + seg*8);
            }
            CPA_COMMIT();
        }
        #pragma unroll
        for (int ks=0;ks<2;ks++){
            uint32_t ah[2][4], bh[8], bl[8];
            #pragma unroll
            for (int mt=0;mt<2;mt++)
                ldA(ah[mt], base+bb, wm*32+mt*16, ks*16, 40);
            #pragma unroll
            for (int n2=0;n2<2;n2++){
                ldB(bh+n2*4, base+bb+10240, wn*32+n2*16, ks*16, 40);
                ldB(bl+n2*4, base+bb+15360, wn*32+n2*16, ks*16, 40);
            }
            #pragma unroll
            for (int mt=0;mt<2;mt++)
                #pragma unroll
                for (int nt=0;nt<4;nt++){
                    MMA(s[mt][nt], ah[mt], bh+nt*2);
                    MMA(s[mt][nt], ah[mt], bl+nt*2);
                }
        }
        __syncthreads();
    }
    int which = n0/768, rem = n0 - which*768;
    int bhq = (m0>>11)*HNUM + (rem>>6);
    int tok0 = m0 & 2047;
    #pragma unroll
    for (int mt=0;mt<2;mt++)
        #pragma unroll
        for (int nt=0;nt<4;nt++){
            int d0 = wn*32 + nt*8 + tig*2;
            if (which==2){
                #pragma unroll
                for (int c=0;c<4;c++){
                    int tok = tok0 + wm*32 + mt*16 + (c>>1)*8 + gid;
                    int d = d0 + (c&1);
                    g_Vh[((size_t)bhq*DHEAD + d)*NSEQ + tok] = __float2half_rn(s[mt][nt][c]);
                }
            } else {
                float sc = (which==0) ? QSE : 1.0f;
                __half* Ah = (which==0) ? g_Qh : g_Kh;
                #pragma unroll
                for (int rh=0;rh<2;rh++){
                    int tok = tok0 + wm*32 + mt*16 + rh*8 + gid;
                    size_t o = ((size_t)bhq*NSEQ + tok)*DHEAD + d0;
                    *(uint32_t*)(Ah+o) = pk2(s[mt][nt][rh*2+0]*sc, s[mt][nt][rh*2+1]*sc);
                }
            }
        }
}

// ---------------- HMMA proj GEMM: 3-pass, k-chunk 32, double-buffered ------
// per buf (bytes): Ah 0 (10240), Al 10240 (10240), Bh 20480 (5120), Bl 25600 (5120) = 30720
#define PROJ_SMEM (61440)
__global__ __launch_bounds__(256) void gemm_proj(const float* __restrict__ bias,
                                                 float* __restrict__ Out){
    extern __shared__ __half smp[];
    int tid = threadIdx.x, wid = tid>>5, lane = tid&31;
    int wm = wid>>1, wn = wid&1, gid = lane>>2, tig = lane&3;
    int m0 = blockIdx.y*128, n0 = blockIdx.x*64;
    uint32_t base = smem_u32(smp);
    float s[2][4][4];
    #pragma unroll
    for (int a=0;a<2;a++)
        #pragma unroll
        for (int b=0;b<4;b++)
            #pragma unroll
            for (int c=0;c<4;c++) s[a][b][c]=0.f;

    #pragma unroll
    for (int i=0;i<4;i++){
        int id = tid + i*256;
        int arr = id>>9, rem = id&511, r = rem>>2, seg = rem&3;
        CPA16(base + (uint32_t)(arr*10240 + r*80 + seg*16),
              (arr ? g_Cl : g_Ch) + (size_t)(m0+r)*768 + seg*8);
    }
    #pragma unroll
    for (int i=0;i<2;i++){
        int id = tid + i*256;
        int arr = id>>8, rem = id&255, r = rem>>2, seg = rem&3;
        CPA16(base + (uint32_t)(20480 + arr*5120 + r*80 + seg*16),
              (arr ? g_wpl : g_wph) + (size_t)(n0+r)*768 + seg*8);
    }
    CPA_COMMIT();

    for (int k=0;k<24;k++){
        uint32_t bb = (uint32_t)(k&1)*30720u;
        CPA_WAIT0();
        __syncthreads();
        if (k<23){
            uint32_t nb = (uint32_t)((k+1)&1)*30720u;
            int k0 = (k+1)*32;
            #pragma unroll
            for (int i=0;i<4;i++){
                int id = tid + i*256;
                int arr = id>>9, rem = id&511, r = rem>>2, seg = rem&3;
                CPA16(base + nb + (uint32_t)(arr*10240 + r*80 + seg*16),
                      (arr ? g_Cl : g_Ch) + (size_t)(m0+r)*768 + k0 + seg*8);
            }
            #pragma unroll
            for (int i=0;i<2;i++){
                int id = tid + i*256;
                int arr = id>>8, rem = id&255, r = rem>>2, seg = rem&3;
                CPA16(base + nb + (uint32_t)(20480 + arr*5120 + r*80 + seg*16),
                      (arr ? g_wpl : g_wph) + (size_t)(n0+r)*768 + k0 + seg*8);
            }
            CPA_COMMIT();
        }
        #pragma unroll
        for (int ks=0;ks<2;ks++){
            uint32_t ah[2][4], al[2][4], bh[8], bl[8];
            #pragma unroll
            for (int mt=0;mt<2;mt++){
                ldA(ah[mt], base+bb,       wm*32+mt*16, ks*16, 40);
                ldA(al[mt], base+bb+10240, wm*32+mt*16, ks*16, 40);
            }
            #pragma unroll
            for (int n2=0;n2<2;n2++){
                ldB(bh+n2*4, base+bb+20480, wn*32+n2*16, ks*16, 40);
                ldB(bl+n2*4, base+bb+25600, wn*32+n2*16, ks*16, 40);
            }
            #pragma unroll
            for (int mt=0;mt<2;mt++)
                #pragma unroll
                for (int nt=0;nt<4;nt++){
                    MMA(s[mt][nt], ah[mt], bh+nt*2);
                    MMA(s[mt][nt], al[mt], bh+nt*2);
                    MMA(s[mt][nt], ah[mt], bl+nt*2);
                }
        }
        __syncthreads();
    }
    #pragma unroll
    for (int mt=0;mt<2;mt++)
        #pragma unroll
        for (int nt=0;nt<4;nt++)
            #pragma unroll
            for (int c=0;c<4;c++){
                int row = m0 + wm*32 + mt*16 + (c>>1)*8 + gid;
                int col = n0 + wn*32 + nt*8 + tig*2 + (c&1);
                Out[(size_t)row*768 + col] = s[mt][nt][c] + bias[col];
            }
}

// ---------------- HMMA attention: fp16 QK + fp16 V, 3 CTAs/SM (R13, proven)
#define ATTN_SMEM (73728)
__global__ __launch_bounds__(256, 3) void attn_hm(){
    extern __shared__ __half sh[];
    uint32_t base = smem_u32(sh);
    int tid = threadIdx.x, wid = tid>>5, lane = tid&31;
    int wm = wid>>1, wn = wid&1, gid = lane>>2, tig = lane&3;
    int bh = blockIdx.y, b = bh/HNUM, hq = bh - b*HNUM;
    int row0 = blockIdx.x*128;

    #pragma unroll
    for (int i=0;i<4;i++){
        int id = tid + i*256;
        int r = id>>3, seg = id&7;
        CPA16(base + (uint32_t)(r*144 + seg*16),
              g_Qh + ((size_t)bh*NSEQ + row0 + r)*DHEAD + seg*8);
    }
    #pragma unroll
    for (int i=0;i<4;i++){
        int id = tid + i*256;
        int arr = id>>9, rem = id&511, r = rem>>3, seg = rem&7;
        const __half* src = arr ? g_Vh + ((size_t)bh*DHEAD + r)*NSEQ + seg*8
                                : g_Kh + ((size_t)bh*NSEQ + r)*DHEAD + seg*8;
        CPA16(base + (uint32_t)(36864 + arr*9216 + r*144 + seg*16), src);
    }
    CPA_COMMIT();

    float o[2][4][4], ls[2][2];
    #pragma unroll
    for (int mt=0;mt<2;mt++){ ls[mt][0]=0.f; ls[mt][1]=0.f;
        #pragma unroll
        for (int nt=0;nt<4;nt++)
            #pragma unroll
            for (int c=0;c<4;c++) o[mt][nt][c]=0.f; }
    const unsigned* mp[2][2];
    #pragma unroll
    for (int mt=0;mt<2;mt++)
        #pragma unroll
        for (int rh=0;rh<2;rh++)
            mp[mt][rh] = g_maskbits + (size_t)(row0 + wm*32 + mt*16 + rh*8 + gid)*64 + wn;

    CPA_WAIT0();
    __syncthreads();

    for (int t=0;t<32;t++){
        uint32_t cb = 36864u + (uint32_t)(t&1)*18432u;
        if (t<31){
            uint32_t nb = 36864u + (uint32_t)((t+1)&1)*18432u;
            #pragma unroll
            for (int i=0;i<4;i++){
                int id = tid + i*256;
                int arr = id>>9, rem = id&511, r = rem>>3, seg = rem&7;
                const __half* src = arr ? g_Vh + ((size_t)bh*DHEAD + r)*NSEQ + (t+1)*64 + seg*8
                                        : g_Kh + ((size_t)bh*NSEQ + (t+1)*64 + r)*DHEAD + seg*8;
                CPA16(base + nb + (uint32_t)(arr*9216 + r*144 + seg*16), src);
            }
            CPA_COMMIT();
        }
        float s[2][4][4];
        #pragma unroll
        for (int mt=0;mt<2;mt++)
            #pragma unroll
            for (int nt=0;nt<4;nt++)
                #pragma unroll
                for (int c=0;c<4;c++) s[mt][nt][c]=0.f;
        #pragma unroll
        for (int ks=0;ks<4;ks++){
            uint32_t qh[2][4], kh[8];
            #pragma unroll
            for (int mt=0;mt<2;mt++)
                ldA(qh[mt], base, wm*32+mt*16, ks*16, 72);
            #pragma unroll
            for (int n2=0;n2<2;n2++)
                ldB(kh+n2*4, base+cb, wn*32+n2*16, ks*16, 72);
            #pragma unroll
            for (int mt=0;mt<2;mt++)
                #pragma unroll
                for (int nt=0;nt<4;nt++)
                    MMA(s[mt][nt], qh[mt], kh+nt*2);
        }
        #pragma unroll
        for (int mt=0;mt<2;mt++){
            unsigned w0 = mp[mt][0][t*2];
            unsigned w1 = mp[mt][1][t*2];
            int r0 = wm*32 + mt*16 + gid;
            #pragma unroll
            for (int nt=0;nt<4;nt++){
                int bb = nt*8 + tig*2;
                float p0 = ((w0>>bb)&1u)     ? 0.f : ex2f(fminf(s[mt][nt][0],14.f));
                float p1 = ((w0>>(bb+1))&1u) ? 0.f : ex2f(fminf(s[mt][nt][1],14.f));
                float p2 = ((w1>>bb)&1u)     ? 0.f : ex2f(fminf(s[mt][nt][2],14.f));
                float p3 = ((w1>>(bb+1))&1u) ? 0.f : ex2f(fminf(s[mt][nt][3],14.f));
                ls[mt][0] += p0+p1; ls[mt][1] += p2+p3;
                int col = wn*32 + nt*8 + tig*2;
                *(uint32_t*)(sh + 9216 + r0*72 + col)     = pk2(p0,p1);
                *(uint32_t*)(sh + 9216 + (r0+8)*72 + col) = pk2(p2,p3);
            }
        }
        __syncthreads();
        #pragma unroll
        for (int ks=0;ks<4;ks++){
            uint32_t pa[2][4], vh[8];
            #pragma unroll
            for (int mt=0;mt<2;mt++)
                ldA(pa[mt], base+18432, wm*32+mt*16, ks*16, 72);
            #pragma unroll
            for (int n2=0;n2<2;n2++)
                ldB(vh+n2*4, base+cb+9216, wn*32+n2*16, ks*16, 72);
            #pragma unroll
            for (int mt=0;mt<2;mt++)
                #pragma unroll
                for (int nt=0;nt<4;nt++)
                    MMA(o[mt][nt], pa[mt], vh+nt*2);
        }
        if (t<31) CPA_WAIT0();
        __syncthreads();
    }
    #pragma unroll
    for (int mt=0;mt<2;mt++)
        #pragma unroll
        for (int rh=0;rh<2;rh++){
            ls[mt][rh] += __shfl_xor_sync(0xffffffffu, ls[mt][rh], 1);
            ls[mt][rh] += __shfl_xor_sync(0xffffffffu, ls[mt][rh], 2);
        }
    float* lbuf = (float*)sh;
    if (tig==0){
        #pragma unroll
        for (int mt=0;mt<2;mt++)
            #pragma unroll
            for (int rh=0;rh<2;rh++)
                lbuf[wn*128 + wm*32 + mt*16 + rh*8 + gid] = ls[mt][rh];
    }
    __syncthreads();
    float inv[2][2];
    #pragma unroll
    for (int mt=0;mt<2;mt++)
        #pragma unroll
        for (int rh=0;rh<2;rh++){
            int r = wm*32 + mt*16 + rh*8 + gid;
            inv[mt][rh] = 1.0f / fmaxf(lbuf[r] + lbuf[128+r], 1e-30f);
        }
    #pragma unroll
    for (int mt=0;mt<2;mt++)
        #pragma unroll
        for (int nt=0;nt<4;nt++){
            int d0 = wn*32 + nt*8 + tig*2;
            #pragma unroll
            for (int rh=0;rh<2;rh++){
                float v0 = o[mt][nt][rh*2+0]*inv[mt][rh];
                float v1 = o[mt][nt][rh*2+1]*inv[mt][rh];
                int row = row0 + wm*32 + mt*16 + rh*8 + gid;
                size_t off = ((size_t)b*NSEQ + row)*CDIM + hq*64 + d0;
                __half h0 = __float2half_rn(v0), h1 = __float2half_rn(v1);
                *(uint32_t*)(g_Ch+off) = pk2(v0,v1);
                *(uint32_t*)(g_Cl+off) = pk2(v0-__half2float(h0), v1-__half2float(h1));
            }
        }
}

// ---------------- launch ----------------
extern "C" void kernel_launch(void* const* d_in, const int* in_sizes, int n_in,
                              void* d_out, int out_size){
    const float* x      = (const float*)d_in[0];
    const void*  mask   = d_in[1];
    const float* w_qkv  = (const float*)d_in[2];
    const float* w_proj = (const float*)d_in[3];
    const float* b_proj = (const float*)d_in[4];
    float* out = (float*)d_out;

    cudaFuncSetAttribute(attn_hm, cudaFuncAttributeMaxDynamicSharedMemorySize, ATTN_SMEM);
    cudaFuncSetAttribute(gemm_proj, cudaFuncAttributeMaxDynamicSharedMemorySize, PROJ_SMEM);

    probe_mask<<<1, 256>>>((const unsigned*)mask);
    mask_pack<<<512, 256>>>(mask);
    splitx<<<6144, 256>>>(x);
    wsplit<<<dim3(72,24), dim3(32,8)>>>(w_qkv, 768, 2304, 0);
    wsplit<<<dim3(24,24), dim3(32,8)>>>(w_proj, 768, 768, 1);
    gemm_qkv<<<dim3(36,64), 256>>>();
    attn_hm<<<dim3(16,48), 256, ATTN_SMEM>>>();
    gemm_proj<<<dim3(12,64), 256, PROJ_SMEM>>>(b_proj, out);
}

// round 15
// speedup vs baseline: 2.5699x; 1.1817x over previous
#include <cuda_runtime.h>
#include <cuda_fp16.h>
#include <cstdint>

#define BB 4
#define NSEQ 2048
#define CDIM 768
#define HNUM 12
#define DHEAD 64
#define QSE 0.18033688011112042f   // 0.125 * log2(e)

// ---------------- scratch ----------------
__device__ unsigned g_maskbits[NSEQ * (NSEQ / 32)];
__device__ int g_mask_mode;
__device__ __half g_xh[8192*768];
__device__ __half g_wqh[2304*768];
__device__ __half g_wph[768*768],  g_wpl[768*768];
__device__ __half g_Qh[48*2048*64];                     // [bh][tok][d], scaled, fp16
__device__ __half g_Kh[48*2048*64];                     // [bh][tok][d], fp16
__device__ __half g_Vh[48*64*2048];                     // [bh][d][tok], fp16
__device__ __half g_Ch[8192*768];                       // ctx fp16

// ---------------- helpers ----------------
__device__ __forceinline__ uint32_t smem_u32(const void* p){
    uint32_t a; asm("{ .reg .u64 t; cvta.to.shared.u64 t, %1; cvt.u32.u64 %0, t; }":"=r"(a):"l"(p)); return a;
}
__device__ __forceinline__ float ex2f(float x){ float r; asm("ex2.approx.f32 %0,%1;":"=f"(r):"f"(x)); return r; }
__device__ __forceinline__ uint32_t pk2(float a, float b){ __half2 h=__floats2half2_rn(a,b); return *(uint32_t*)&h; }

#define CPA16(dst, src) asm volatile("cp.async.cg.shared.global [%0], [%1], 16;\n"::"r"(dst),"l"(src):"memory")
#define CPA_COMMIT()    asm volatile("cp.async.commit_group;\n":::"memory")
#define CPA_WAIT0()     asm volatile("cp.async.wait_group 0;\n":::"memory")

#define LDSM4(r0,r1,r2,r3,ad) asm volatile("ldmatrix.sync.aligned.m8n8.x4.shared.b16 {%0,%1,%2,%3},[%4];":"=r"(r0),"=r"(r1),"=r"(r2),"=r"(r3):"r"(ad))
#define MMA(d,a,b) asm volatile("mma.sync.aligned.m16n8k16.row.col.f32.f16.f16.f32 {%0,%1,%2,%3},{%4,%5,%6,%7},{%8,%9},{%0,%1,%2,%3};" \
    :"+f"((d)[0]),"+f"((d)[1]),"+f"((d)[2]),"+f"((d)[3]) \
    :"r"((a)[0]),"r"((a)[1]),"r"((a)[2]),"r"((a)[3]),"r"((b)[0]),"r"((b)[1]))

__device__ __forceinline__ void ldA(uint32_t* a, uint32_t base, int rb, int kc, int P){
    int l = threadIdx.x & 31;
    uint32_t ad = base + (uint32_t)((rb + (l&7) + ((l>>3)&1)*8)*P + kc + (l>>4)*8)*2;
    LDSM4(a[0],a[1],a[2],a[3],ad);
}
__device__ __forceinline__ void ldB(uint32_t* b, uint32_t base, int nb, int kc, int P){
    int l = threadIdx.x & 31;
    uint32_t ad = base + (uint32_t)((nb + (l&7) + (l>>4)*8)*P + kc + ((l>>3)&1)*8)*2;
    LDSM4(b[0],b[1],b[2],b[3],ad);
}

// ---------------- mask probe + pack ----------------
__global__ void probe_mask(const unsigned* __restrict__ mw) {
    __shared__ int s_not01, s_notfloat;
    int tid = threadIdx.x;
    if (tid == 0) { s_not01 = 0; s_notfloat = 0; }
    __syncthreads();
    unsigned v = mw[tid];
    if (v != 0u && v != 1u) s_not01 = 1;
    if (v != 0u && v != 0x3F800000u) s_notfloat = 1;
    __syncthreads();
    if (tid == 0) g_mask_mode = (!s_not01) ? 0 : (!s_notfloat ? 1 : 2);
}
__global__ void mask_pack(const void* __restrict__ mask) {
    int gid = blockIdx.x * 256 + threadIdx.x;
    if (gid >= NSEQ * (NSEQ / 32)) return;
    long base = (long)(gid >> 6) * NSEQ + (long)(gid & 63) * 32;
    int mode = g_mask_mode;
    unsigned bits = 0u;
    if (mode == 0) {
        const int* p = (const int*)mask;
        #pragma unroll
        for (int j = 0; j < 32; j++) if (p[base + j] != 0) bits |= (1u << j);
    } else if (mode == 1) {
        const float* p = (const float*)mask;
        #pragma unroll
        for (int j = 0; j < 32; j++) if (p[base + j] != 0.0f) bits |= (1u << j);
    } else {
        const unsigned char* p = (const unsigned char*)mask;
        #pragma unroll
        for (int j = 0; j < 32; j++) if (p[base + j] != 0) bits |= (1u << j);
    }
    g_maskbits[gid] = bits;
}

// ---------------- round x to fp16 ----------------
__global__ void splitx(const float* __restrict__ x){
    size_t i = ((size_t)blockIdx.x*256 + threadIdx.x)*4;
    float4 v = *(const float4*)(x + i);
    uint2 hv; hv.x = pk2(v.x, v.y); hv.y = pk2(v.z, v.w);
    *(uint2*)(g_xh + i) = hv;
}
// qkv weight: hi only. proj weight: hi/lo split.
__global__ void wprep(const float* __restrict__ W, int K, int N, int sel){
    __shared__ float t[32][33];
    int k0 = blockIdx.y*32, n0 = blockIdx.x*32;
    int tx = threadIdx.x, ty = threadIdx.y;
    #pragma unroll
    for (int i=0;i<4;i++) t[ty+i*8][tx] = W[(size_t)(k0+ty+i*8)*N + n0+tx];
    __syncthreads();
    #pragma unroll
    for (int i=0;i<4;i++){
        float v = t[tx][ty+i*8];
        size_t o = (size_t)(n0+ty+i*8)*K + k0+tx;
        if (sel){
            __half h = __float2half_rn(v);
            g_wph[o] = h; g_wpl[o] = __float2half_rn(v - __half2float(h));
        } else {
            g_wqh[o] = __float2half_rn(v);
        }
    }
}

// ---------------- HMMA qkv GEMM: 1-pass, k-chunk 32, double-buffered -------
// per buf (bytes): Ah 0 (10240), Bh 10240 (5120) = 15360
__global__ __launch_bounds__(256) void gemm_qkv(){
    __shared__ __half sm[15360];
    int tid = threadIdx.x, wid = tid>>5, lane = tid&31;
    int wm = wid>>1, wn = wid&1, gid = lane>>2, tig = lane&3;
    int m0 = blockIdx.y*128, n0 = blockIdx.x*64;
    uint32_t base = smem_u32(sm);
    float s[2][4][4];
    #pragma unroll
    for (int a=0;a<2;a++)
        #pragma unroll
        for (int b=0;b<4;b++)
            #pragma unroll
            for (int c=0;c<4;c++) s[a][b][c]=0.f;

    #pragma unroll
    for (int i=0;i<2;i++){
        int id = tid + i*256;
        int r = id>>2, seg = id&3;
        CPA16(base + (uint32_t)(r*80 + seg*16), g_xh + (size_t)(m0+r)*768 + seg*8);
    }
    {
        int r = tid>>2, seg = tid&3;
        CPA16(base + (uint32_t)(10240 + r*80 + seg*16), g_wqh + (size_t)(n0+r)*768 + seg*8);
    }
    CPA_COMMIT();

    for (int k=0;k<24;k++){
        uint32_t bb = (uint32_t)(k&1)*15360u;
        CPA_WAIT0();
        __syncthreads();
        if (k<23){
            uint32_t nb = (uint32_t)((k+1)&1)*15360u;
            int k0 = (k+1)*32;
            #pragma unroll
            for (int i=0;i<2;i++){
                int id = tid + i*256;
                int r = id>>2, seg = id&3;
                CPA16(base + nb + (uint32_t)(r*80 + seg*16),
                      g_xh + (size_t)(m0+r)*768 + k0 + seg*8);
            }
            {
                int r = tid>>2, seg = tid&3;
                CPA16(base + nb + (uint32_t)(10240 + r*80 + seg*16),
                      g_wqh + (size_t)(n0+r)*768 + k0 + seg*8);
            }
            CPA_COMMIT();
        }
        #pragma unroll
        for (int ks=0;ks<2;ks++){
            uint32_t ah[2][4], bh[8];
            #pragma unroll
            for (int mt=0;mt<2;mt++)
                ldA(ah[mt], base+bb, wm*32+mt*16, ks*16, 40);
            #pragma unroll
            for (int n2=0;n2<2;n2++)
                ldB(bh+n2*4, base+bb+10240, wn*32+n2*16, ks*16, 40);
            #pragma unroll
            for (int mt=0;mt<2;mt++)
                #pragma unroll
                for (int nt=0;nt<4;nt++)
                    MMA(s[mt][nt], ah[mt], bh+nt*2);
        }
        __syncthreads();
    }
    int which = n0/768, rem = n0 - which*768;
    int bhq = (m0>>11)*HNUM + (rem>>6);
    int tok0 = m0 & 2047;
    #pragma unroll
    for (int mt=0;mt<2;mt++)
        #pragma unroll
        for (int nt=0;nt<4;nt++){
            int d0 = wn*32 + nt*8 + tig*2;
            if (which==2){
                #pragma unroll
                for (int c=0;c<4;c++){
                    int tok = tok0 + wm*32 + mt*16 + (c>>1)*8 + gid;
                    int d = d0 + (c&1);
                    g_Vh[((size_t)bhq*DHEAD + d)*NSEQ + tok] = __float2half_rn(s[mt][nt][c]);
                }
            } else {
                float sc = (which==0) ? QSE : 1.0f;
                __half* Ah = (which==0) ? g_Qh : g_Kh;
                #pragma unroll
                for (int rh=0;rh<2;rh++){
                    int tok = tok0 + wm*32 + mt*16 + rh*8 + gid;
                    size_t o = ((size_t)bhq*NSEQ + tok)*DHEAD + d0;
                    *(uint32_t*)(Ah+o) = pk2(s[mt][nt][rh*2+0]*sc, s[mt][nt][rh*2+1]*sc);
                }
            }
        }
}

// ---------------- HMMA proj GEMM: 2-pass (Ch*Wh + Ch*Wl), k-chunk 32 -------
// per buf (bytes): Ah 0 (10240), Bh 10240 (5120), Bl 15360 (5120) = 20480
__global__ __launch_bounds__(256) void gemm_proj(const float* __restrict__ bias,
                                                 float* __restrict__ Out){
    __shared__ __half sm[20480];
    int tid = threadIdx.x, wid = tid>>5, lane = tid&31;
    int wm = wid>>1, wn = wid&1, gid = lane>>2, tig = lane&3;
    int m0 = blockIdx.y*128, n0 = blockIdx.x*64;
    uint32_t base = smem_u32(sm);
    float s[2][4][4];
    #pragma unroll
    for (int a=0;a<2;a++)
        #pragma unroll
        for (int b=0;b<4;b++)
            #pragma unroll
            for (int c=0;c<4;c++) s[a][b][c]=0.f;

    #pragma unroll
    for (int i=0;i<2;i++){
        int id = tid + i*256;
        int r = id>>2, seg = id&3;
        CPA16(base + (uint32_t)(r*80 + seg*16), g_Ch + (size_t)(m0+r)*768 + seg*8);
    }
    {
        int arr = tid>>7, rem = tid&127;     // 128 thr each for Bh rows 0..31? no:
    }
    // B staging: 64 rows x 4 segs = 256 loads for Bh, 256 for Bl
    {
        int r = tid>>2, seg = tid&3;
        CPA16(base + (uint32_t)(10240 + r*80 + seg*16), g_wph + (size_t)(n0+r)*768 + seg*8);
        CPA16(base + (uint32_t)(15360 + r*80 + seg*16), g_wpl + (size_t)(n0+r)*768 + seg*8);
    }
    CPA_COMMIT();

    for (int k=0;k<24;k++){
        uint32_t bb = (uint32_t)(k&1)*20480u;
        CPA_WAIT0();
        __syncthreads();
        if (k<23){
            uint32_t nb = (uint32_t)((k+1)&1)*20480u;
            int k0 = (k+1)*32;
            #pragma unroll
            for (int i=0;i<2;i++){
                int id = tid + i*256;
                int r = id>>2, seg = id&3;
                CPA16(base + nb + (uint32_t)(r*80 + seg*16),
                      g_Ch + (size_t)(m0+r)*768 + k0 + seg*8);
            }
            {
                int r = tid>>2, seg = tid&3;
                CPA16(base + nb + (uint32_t)(10240 + r*80 + seg*16),
                      g_wph + (size_t)(n0+r)*768 + k0 + seg*8);
                CPA16(base + nb + (uint32_t)(15360 + r*80 + seg*16),
                      g_wpl + (size_t)(n0+r)*768 + k0 + seg*8);
            }
            CPA_COMMIT();
        }
        #pragma unroll
        for (int ks=0;ks<2;ks++){
            uint32_t ah[2][4], bh[8], bl[8];
            #pragma unroll
            for (int mt=0;mt<2;mt++)
                ldA(ah[mt], base+bb, wm*32+mt*16, ks*16, 40);
            #pragma unroll
            for (int n2=0;n2<2;n2++){
                ldB(bh+n2*4, base+bb+10240, wn*32+n2*16, ks*16, 40);
                ldB(bl+n2*4, base+bb+15360, wn*32+n2*16, ks*16, 40);
            }
            #pragma unroll
            for (int mt=0;mt<2;mt++)
                #pragma unroll
                for (int nt=0;nt<4;nt++){
                    MMA(s[mt][nt], ah[mt], bh+nt*2);
                    MMA(s[mt][nt], ah[mt], bl+nt*2);
                }
        }
        __syncthreads();
    }
    #pragma unroll
    for (int mt=0;mt<2;mt++)
        #pragma unroll
        for (int nt=0;nt<4;nt++)
            #pragma unroll
            for (int c=0;c<4;c++){
                int row = m0 + wm*32 + mt*16 + (c>>1)*8 + gid;
                int col = n0 + wn*32 + nt*8 + tig*2 + (c&1);
                Out[(size_t)row*768 + col] = s[mt][nt][c] + bias[col];
            }
}

// ---------------- HMMA attention: fp16 QK + fp16 V, 3 CTAs/SM (proven) -----
#define ATTN_SMEM (73728)
__global__ __launch_bounds__(256, 3) void attn_hm(){
    extern __shared__ __half sh[];
    uint32_t base = smem_u32(sh);
    int tid = threadIdx.x, wid = tid>>5, lane = tid&31;
    int wm = wid>>1, wn = wid&1, gid = lane>>2, tig = lane&3;
    int bh = blockIdx.y, b = bh/HNUM, hq = bh - b*HNUM;
    int row0 = blockIdx.x*128;

    #pragma unroll
    for (int i=0;i<4;i++){
        int id = tid + i*256;
        int r = id>>3, seg = id&7;
        CPA16(base + (uint32_t)(r*144 + seg*16),
              g_Qh + ((size_t)bh*NSEQ + row0 + r)*DHEAD + seg*8);
    }
    #pragma unroll
    for (int i=0;i<4;i++){
        int id = tid + i*256;
        int arr = id>>9, rem = id&511, r = rem>>3, seg = rem&7;
        const __half* src = arr ? g_Vh + ((size_t)bh*DHEAD + r)*NSEQ + seg*8
                                : g_Kh + ((size_t)bh*NSEQ + r)*DHEAD + seg*8;
        CPA16(base + (uint32_t)(36864 + arr*9216 + r*144 + seg*16), src);
    }
    CPA_COMMIT();

    float o[2][4][4], ls[2][2];
    #pragma unroll
    for (int mt=0;mt<2;mt++){ ls[mt][0]=0.f; ls[mt][1]=0.f;
        #pragma unroll
        for (int nt=0;nt<4;nt++)
            #pragma unroll
            for (int c=0;c<4;c++) o[mt][nt][c]=0.f; }
    const unsigned* mp[2][2];
    #pragma unroll
    for (int mt=0;mt<2;mt++)
        #pragma unroll
        for (int rh=0;rh<2;rh++)
            mp[mt][rh] = g_maskbits + (size_t)(row0 + wm*32 + mt*16 + rh*8 + gid)*64 + wn;

    CPA_WAIT0();
    __syncthreads();

    for (int t=0;t<32;t++){
        uint32_t cb = 36864u + (uint32_t)(t&1)*18432u;
        if (t<31){
            uint32_t nb = 36864u + (uint32_t)((t+1)&1)*18432u;
            #pragma unroll
            for (int i=0;i<4;i++){
                int id = tid + i*256;
                int arr = id>>9, rem = id&511, r = rem>>3, seg = rem&7;
                const __half* src = arr ? g_Vh + ((size_t)bh*DHEAD + r)*NSEQ + (t+1)*64 + seg*8
                                        : g_Kh + ((size_t)bh*NSEQ + (t+1)*64 + r)*DHEAD + seg*8;
                CPA16(base + nb + (uint32_t)(arr*9216 + r*144 + seg*16), src);
            }
            CPA_COMMIT();
        }
        float s[2][4][4];
        #pragma unroll
        for (int mt=0;mt<2;mt++)
            #pragma unroll
            for (int nt=0;nt<4;nt++)
                #pragma unroll
                for (int c=0;c<4;c++) s[mt][nt][c]=0.f;
        #pragma unroll
        for (int ks=0;ks<4;ks++){
            uint32_t qh[2][4], kh[8];
            #pragma unroll
            for (int mt=0;mt<2;mt++)
                ldA(qh[mt], base, wm*32+mt*16, ks*16, 72);
            #pragma unroll
            for (int n2=0;n2<2;n2++)
                ldB(kh+n2*4, base+cb, wn*32+n2*16, ks*16, 72);
            #pragma unroll
            for (int mt=0;mt<2;mt++)
                #pragma unroll
                for (int nt=0;nt<4;nt++)
                    MMA(s[mt][nt], qh[mt], kh+nt*2);
        }
        #pragma unroll
        for (int mt=0;mt<2;mt++){
            unsigned w0 = mp[mt][0][t*2];
            unsigned w1 = mp[mt][1][t*2];
            int r0 = wm*32 + mt*16 + gid;
            #pragma unroll
            for (int nt=0;nt<4;nt++){
                int bb = nt*8 + tig*2;
                float p0 = ((w0>>bb)&1u)     ? 0.f : ex2f(fminf(s[mt][nt][0],14.f));
                float p1 = ((w0>>(bb+1))&1u) ? 0.f : ex2f(fminf(s[mt][nt][1],14.f));
                float p2 = ((w1>>bb)&1u)     ? 0.f : ex2f(fminf(s[mt][nt][2],14.f));
                float p3 = ((w1>>(bb+1))&1u) ? 0.f : ex2f(fminf(s[mt][nt][3],14.f));
                ls[mt][0] += p0+p1; ls[mt][1] += p2+p3;
                int col = wn*32 + nt*8 + tig*2;
                *(uint32_t*)(sh + 9216 + r0*72 + col)     = pk2(p0,p1);
                *(uint32_t*)(sh + 9216 + (r0+8)*72 + col) = pk2(p2,p3);
            }
        }
        __syncthreads();
        #pragma unroll
        for (int ks=0;ks<4;ks++){
            uint32_t pa[2][4], vh[8];
            #pragma unroll
            for (int mt=0;mt<2;mt++)
                ldA(pa[mt], base+18432, wm*32+mt*16, ks*16, 72);
            #pragma unroll
            for (int n2=0;n2<2;n2++)
                ldB(vh+n2*4, base+cb+9216, wn*32+n2*16, ks*16, 72);
            #pragma unroll
            for (int mt=0;mt<2;mt++)
                #pragma unroll
                for (int nt=0;nt<4;nt++)
                    MMA(o[mt][nt], pa[mt], vh+nt*2);
        }
        if (t<31) CPA_WAIT0();
        __syncthreads();
    }
    #pragma unroll
    for (int mt=0;mt<2;mt++)
        #pragma unroll
        for (int rh=0;rh<2;rh++){
            ls[mt][rh] += __shfl_xor_sync(0xffffffffu, ls[mt][rh], 1);
            ls[mt][rh] += __shfl_xor_sync(0xffffffffu, ls[mt][rh], 2);
        }
    float* lbuf = (float*)sh;
    if (tig==0){
        #pragma unroll
        for (int mt=0;mt<2;mt++)
            #pragma unroll
            for (int rh=0;rh<2;rh++)
                lbuf[wn*128 + wm*32 + mt*16 + rh*8 + gid] = ls[mt][rh];
    }
    __syncthreads();
    float inv[2][2];
    #pragma unroll
    for (int mt=0;mt<2;mt++)
        #pragma unroll
        for (int rh=0;rh<2;rh++){
            int r = wm*32 + mt*16 + rh*8 + gid;
            inv[mt][rh] = 1.0f / fmaxf(lbuf[r] + lbuf[128+r], 1e-30f);
        }
    #pragma unroll
    for (int mt=0;mt<2;mt++)
        #pragma unroll
        for (int nt=0;nt<4;nt++){
            int d0 = wn*32 + nt*8 + tig*2;
            #pragma unroll
            for (int rh=0;rh<2;rh++){
                float v0 = o[mt][nt][rh*2+0]*inv[mt][rh];
                float v1 = o[mt][nt][rh*2+1]*inv[mt][rh];
                int row = row0 + wm*32 + mt*16 + rh*8 + gid;
                size_t off = ((size_t)b*NSEQ + row)*CDIM + hq*64 + d0;
                *(uint32_t*)(g_Ch+off) = pk2(v0,v1);
            }
        }
}

// ---------------- launch ----------------
extern "C" void kernel_launch(void* const* d_in, const int* in_sizes, int n_in,
                              void* d_out, int out_size){
    const float* x      = (const float*)d_in[0];
    const void*  mask   = d_in[1];
    const float* w_qkv  = (const float*)d_in[2];
    const float* w_proj = (const float*)d_in[3];
    const float* b_proj = (const float*)d_in[4];
    float* out = (float*)d_out;

    cudaFuncSetAttribute(attn_hm, cudaFuncAttributeMaxDynamicSharedMemorySize, ATTN_SMEM);

    probe_mask<<<1, 256>>>((const unsigned*)mask);
    mask_pack<<<512, 256>>>(mask);
    splitx<<<6144, 256>>>(x);
    wprep<<<dim3(72,24), dim3(32,8)>>>(w_qkv, 768, 2304, 0);
    wprep<<<dim3(24,24), dim3(32,8)>>>(w_proj, 768, 768, 1);
    gemm_qkv<<<dim3(36,64), 256>>>();
    attn_hm<<<dim3(16,48), 256, ATTN_SMEM>>>();
    gemm_proj<<<dim3(12,64), 256>>>(b_proj, out);
}

// round 16
// speedup vs baseline: 2.7340x; 1.0639x over previous
#include <cuda_runtime.h>
#include <cuda_fp16.h>
#include <cstdint>

#define BB 4
#define NSEQ 2048
#define CDIM 768
#define HNUM 12
#define DHEAD 64
#define QSE 0.18033688011112042f   // 0.125 * log2(e)

// ---------------- scratch ----------------
__device__ unsigned g_maskbits[NSEQ * (NSEQ / 32)];
__device__ int g_mask_mode;
__device__ __half g_xh[8192*768];
__device__ __half g_wqh[2304*768];
__device__ __half g_wph[768*768],  g_wpl[768*768];
__device__ __half g_Qh[48*2048*64];                     // [bh][tok][d], scaled, fp16
__device__ __half g_Kh[48*2048*64];                     // [bh][tok][d], fp16
__device__ __half g_Vh[48*64*2048];                     // [bh][d][tok], fp16
__device__ __half g_Ch[8192*768];                       // ctx fp16

// ---------------- helpers ----------------
__device__ __forceinline__ uint32_t smem_u32(const void* p){
    uint32_t a; asm("{ .reg .u64 t; cvta.to.shared.u64 t, %1; cvt.u32.u64 %0, t; }":"=r"(a):"l"(p)); return a;
}
__device__ __forceinline__ uint32_t pk2(float a, float b){ __half2 h=__floats2half2_rn(a,b); return *(uint32_t*)&h; }
// exp2 of two floats via fp16x2 MUFU, clamped at 14.0 (0x4B00)
__device__ __forceinline__ uint32_t exp2h2(float a, float b){
    __half2 h = __floats2half2_rn(a, b);
    uint32_t u = *(uint32_t*)&h;
    asm("min.f16x2 %0, %0, %1;" : "+r"(u) : "r"(0x4B004B00u));
    asm("ex2.approx.f16x2 %0, %0;" : "+r"(u));
    return u;
}

#define CPA16(dst, src) asm volatile("cp.async.cg.shared.global [%0], [%1], 16;\n"::"r"(dst),"l"(src):"memory")
#define CPA_COMMIT()    asm volatile("cp.async.commit_group;\n":::"memory")
#define CPA_WAIT0()     asm volatile("cp.async.wait_group 0;\n":::"memory")

#define LDSM4(r0,r1,r2,r3,ad) asm volatile("ldmatrix.sync.aligned.m8n8.x4.shared.b16 {%0,%1,%2,%3},[%4];":"=r"(r0),"=r"(r1),"=r"(r2),"=r"(r3):"r"(ad))
#define MMA(d,a,b) asm volatile("mma.sync.aligned.m16n8k16.row.col.f32.f16.f16.f32 {%0,%1,%2,%3},{%4,%5,%6,%7},{%8,%9},{%0,%1,%2,%3};" \
    :"+f"((d)[0]),"+f"((d)[1]),"+f"((d)[2]),"+f"((d)[3]) \
    :"r"((a)[0]),"r"((a)[1]),"r"((a)[2]),"r"((a)[3]),"r"((b)[0]),"r"((b)[1]))

__device__ __forceinline__ void ldA(uint32_t* a, uint32_t base, int rb, int kc, int P){
    int l = threadIdx.x & 31;
    uint32_t ad = base + (uint32_t)((rb + (l&7) + ((l>>3)&1)*8)*P + kc + (l>>4)*8)*2;
    LDSM4(a[0],a[1],a[2],a[3],ad);
}
__device__ __forceinline__ void ldB(uint32_t* b, uint32_t base, int nb, int kc, int P){
    int l = threadIdx.x & 31;
    uint32_t ad = base + (uint32_t)((nb + (l&7) + (l>>4)*8)*P + kc + ((l>>3)&1)*8)*2;
    LDSM4(b[0],b[1],b[2],b[3],ad);
}

// ---------------- mask probe + pack ----------------
__global__ void probe_mask(const unsigned* __restrict__ mw) {
    __shared__ int s_not01, s_notfloat;
    int tid = threadIdx.x;
    if (tid == 0) { s_not01 = 0; s_notfloat = 0; }
    __syncthreads();
    unsigned v = mw[tid];
    if (v != 0u && v != 1u) s_not01 = 1;
    if (v != 0u && v != 0x3F800000u) s_notfloat = 1;
    __syncthreads();
    if (tid == 0) g_mask_mode = (!s_not01) ? 0 : (!s_notfloat ? 1 : 2);
}
__global__ void mask_pack(const void* __restrict__ mask) {
    int gid = blockIdx.x * 256 + threadIdx.x;
    if (gid >= NSEQ * (NSEQ / 32)) return;
    long base = (long)(gid >> 6) * NSEQ + (long)(gid & 63) * 32;
    int mode = g_mask_mode;
    unsigned bits = 0u;
    if (mode == 0) {
        const int* p = (const int*)mask;
        #pragma unroll
        for (int j = 0; j < 32; j++) if (p[base + j] != 0) bits |= (1u << j);
    } else if (mode == 1) {
        const float* p = (const float*)mask;
        #pragma unroll
        for (int j = 0; j < 32; j++) if (p[base + j] != 0.0f) bits |= (1u << j);
    } else {
        const unsigned char* p = (const unsigned char*)mask;
        #pragma unroll
        for (int j = 0; j < 32; j++) if (p[base + j] != 0) bits |= (1u << j);
    }
    g_maskbits[gid] = bits;
}

// ---------------- round x to fp16 ----------------
__global__ void splitx(const float* __restrict__ x){
    size_t i = ((size_t)blockIdx.x*256 + threadIdx.x)*4;
    float4 v = *(const float4*)(x + i);
    uint2 hv; hv.x = pk2(v.x, v.y); hv.y = pk2(v.z, v.w);
    *(uint2*)(g_xh + i) = hv;
}
// qkv weight: hi only. proj weight: hi/lo split.
__global__ void wprep(const float* __restrict__ W, int K, int N, int sel){
    __shared__ float t[32][33];
    int k0 = blockIdx.y*32, n0 = blockIdx.x*32;
    int tx = threadIdx.x, ty = threadIdx.y;
    #pragma unroll
    for (int i=0;i<4;i++) t[ty+i*8][tx] = W[(size_t)(k0+ty+i*8)*N + n0+tx];
    __syncthreads();
    #pragma unroll
    for (int i=0;i<4;i++){
        float v = t[tx][ty+i*8];
        size_t o = (size_t)(n0+ty+i*8)*K + k0+tx;
        if (sel){
            __half h = __float2half_rn(v);
            g_wph[o] = h; g_wpl[o] = __float2half_rn(v - __half2float(h));
        } else {
            g_wqh[o] = __float2half_rn(v);
        }
    }
}

// ---------------- HMMA qkv GEMM: 1-pass, k-chunk 64, double-buffered -------
// per buf (bytes): A 0 (18432, 128x72h), B 18432 (9216, 64x72h) = 27648
#define QKV_SMEM (55296)
__global__ __launch_bounds__(256) void gemm_qkv(){
    extern __shared__ __half smq[];
    int tid = threadIdx.x, wid = tid>>5, lane = tid&31;
    int wm = wid>>1, wn = wid&1, gid = lane>>2, tig = lane&3;
    int m0 = blockIdx.y*128, n0 = blockIdx.x*64;
    uint32_t base = smem_u32(smq);
    float s[2][4][4];
    #pragma unroll
    for (int a=0;a<2;a++)
        #pragma unroll
        for (int b=0;b<4;b++)
            #pragma unroll
            for (int c=0;c<4;c++) s[a][b][c]=0.f;

    #pragma unroll
    for (int i=0;i<4;i++){
        int id = tid + i*256;
        int r = id>>3, seg = id&7;
        CPA16(base + (uint32_t)(r*144 + seg*16), g_xh + (size_t)(m0+r)*768 + seg*8);
    }
    #pragma unroll
    for (int i=0;i<2;i++){
        int id = tid + i*256;
        int r = id>>3, seg = id&7;
        CPA16(base + (uint32_t)(18432 + r*144 + seg*16), g_wqh + (size_t)(n0+r)*768 + seg*8);
    }
    CPA_COMMIT();

    for (int k=0;k<12;k++){
        uint32_t bb = (uint32_t)(k&1)*27648u;
        CPA_WAIT0();
        __syncthreads();
        if (k<11){
            uint32_t nb = (uint32_t)((k+1)&1)*27648u;
            int k0 = (k+1)*64;
            #pragma unroll
            for (int i=0;i<4;i++){
                int id = tid + i*256;
                int r = id>>3, seg = id&7;
                CPA16(base + nb + (uint32_t)(r*144 + seg*16),
                      g_xh + (size_t)(m0+r)*768 + k0 + seg*8);
            }
            #pragma unroll
            for (int i=0;i<2;i++){
                int id = tid + i*256;
                int r = id>>3, seg = id&7;
                CPA16(base + nb + (uint32_t)(18432 + r*144 + seg*16),
                      g_wqh + (size_t)(n0+r)*768 + k0 + seg*8);
            }
            CPA_COMMIT();
        }
        #pragma unroll
        for (int ks=0;ks<4;ks++){
            uint32_t ah[2][4], bh[8];
            #pragma unroll
            for (int mt=0;mt<2;mt++)
                ldA(ah[mt], base+bb, wm*32+mt*16, ks*16, 72);
            #pragma unroll
            for (int n2=0;n2<2;n2++)
                ldB(bh+n2*4, base+bb+18432, wn*32+n2*16, ks*16, 72);
            #pragma unroll
            for (int mt=0;mt<2;mt++)
                #pragma unroll
                for (int nt=0;nt<4;nt++)
                    MMA(s[mt][nt], ah[mt], bh+nt*2);
        }
        __syncthreads();
    }
    int which = n0/768, rem = n0 - which*768;
    int bhq = (m0>>11)*HNUM + (rem>>6);
    int tok0 = m0 & 2047;
    #pragma unroll
    for (int mt=0;mt<2;mt++)
        #pragma unroll
        for (int nt=0;nt<4;nt++){
            int d0 = wn*32 + nt*8 + tig*2;
            if (which==2){
                #pragma unroll
                for (int c=0;c<4;c++){
                    int tok = tok0 + wm*32 + mt*16 + (c>>1)*8 + gid;
                    int d = d0 + (c&1);
                    g_Vh[((size_t)bhq*DHEAD + d)*NSEQ + tok] = __float2half_rn(s[mt][nt][c]);
                }
            } else {
                float sc = (which==0) ? QSE : 1.0f;
                __half* Ah = (which==0) ? g_Qh : g_Kh;
                #pragma unroll
                for (int rh=0;rh<2;rh++){
                    int tok = tok0 + wm*32 + mt*16 + rh*8 + gid;
                    size_t o = ((size_t)bhq*NSEQ + tok)*DHEAD + d0;
                    *(uint32_t*)(Ah+o) = pk2(s[mt][nt][rh*2+0]*sc, s[mt][nt][rh*2+1]*sc);
                }
            }
        }
}

// ---------------- HMMA proj GEMM: 2-pass, k-chunk 64, double-buffered ------
// per buf (bytes): A 0 (18432), Bh 18432 (9216), Bl 27648 (9216) = 36864
#define PROJ_SMEM (73728)
__global__ __launch_bounds__(256) void gemm_proj(const float* __restrict__ bias,
                                                 float* __restrict__ Out){
    extern __shared__ __half smp[];
    int tid = threadIdx.x, wid = tid>>5, lane = tid&31;
    int wm = wid>>1, wn = wid&1, gid = lane>>2, tig = lane&3;
    int m0 = blockIdx.y*128, n0 = blockIdx.x*64;
    uint32_t base = smem_u32(smp);
    float s[2][4][4];
    #pragma unroll
    for (int a=0;a<2;a++)
        #pragma unroll
        for (int b=0;b<4;b++)
            #pragma unroll
            for (int c=0;c<4;c++) s[a][b][c]=0.f;

    #pragma unroll
    for (int i=0;i<4;i++){
        int id = tid + i*256;
        int r = id>>3, seg = id&7;
        CPA16(base + (uint32_t)(r*144 + seg*16), g_Ch + (size_t)(m0+r)*768 + seg*8);
    }
    #pragma unroll
    for (int i=0;i<2;i++){
        int id = tid + i*256;
        int r = id>>3, seg = id&7;
        CPA16(base + (uint32_t)(18432 + r*144 + seg*16), g_wph + (size_t)(n0+r)*768 + seg*8);
        CPA16(base + (uint32_t)(27648 + r*144 + seg*16), g_wpl + (size_t)(n0+r)*768 + seg*8);
    }
    CPA_COMMIT();

    for (int k=0;k<12;k++){
        uint32_t bb = (uint32_t)(k&1)*36864u;
        CPA_WAIT0();
        __syncthreads();
        if (k<11){
            uint32_t nb = (uint32_t)((k+1)&1)*36864u;
            int k0 = (k+1)*64;
            #pragma unroll
            for (int i=0;i<4;i++){
                int id = tid + i*256;
                int r = id>>3, seg = id&7;
                CPA16(base + nb + (uint32_t)(r*144 + seg*16),
                      g_Ch + (size_t)(m0+r)*768 + k0 + seg*8);
            }
            #pragma unroll
            for (int i=0;i<2;i++){
                int id = tid + i*256;
                int r = id>>3, seg = id&7;
                CPA16(base + nb + (uint32_t)(18432 + r*144 + seg*16),
                      g_wph + (size_t)(n0+r)*768 + k0 + seg*8);
                CPA16(base + nb + (uint32_t)(27648 + r*144 + seg*16),
                      g_wpl + (size_t)(n0+r)*768 + k0 + seg*8);
            }
            CPA_COMMIT();
        }
        #pragma unroll
        for (int ks=0;ks<4;ks++){
            uint32_t ah[2][4], bh[8], bl[8];
            #pragma unroll
            for (int mt=0;mt<2;mt++)
                ldA(ah[mt], base+bb, wm*32+mt*16, ks*16, 72);
            #pragma unroll
            for (int n2=0;n2<2;n2++){
                ldB(bh+n2*4, base+bb+18432, wn*32+n2*16, ks*16, 72);
                ldB(bl+n2*4, base+bb+27648, wn*32+n2*16, ks*16, 72);
            }
            #pragma unroll
            for (int mt=0;mt<2;mt++)
                #pragma unroll
                for (int nt=0;nt<4;nt++){
                    MMA(s[mt][nt], ah[mt], bh+nt*2);
                    MMA(s[mt][nt], ah[mt], bl+nt*2);
                }
        }
        __syncthreads();
    }
    #pragma unroll
    for (int mt=0;mt<2;mt++)
        #pragma unroll
        for (int nt=0;nt<4;nt++)
            #pragma unroll
            for (int c=0;c<4;c++){
                int row = m0 + wm*32 + mt*16 + (c>>1)*8 + gid;
                int col = n0 + wn*32 + nt*8 + tig*2 + (c&1);
                Out[(size_t)row*768 + col] = s[mt][nt][c] + bias[col];
            }
}

// ---------------- HMMA attention: f16x2 exp softmax, 3 CTAs/SM -------------
#define ATTN_SMEM (73728)
__global__ __launch_bounds__(256, 3) void attn_hm(){
    extern __shared__ __half sh[];
    uint32_t base = smem_u32(sh);
    int tid = threadIdx.x, wid = tid>>5, lane = tid&31;
    int wm = wid>>1, wn = wid&1, gid = lane>>2, tig = lane&3;
    int bh = blockIdx.y, b = bh/HNUM, hq = bh - b*HNUM;
    int row0 = blockIdx.x*128;

    #pragma unroll
    for (int i=0;i<4;i++){
        int id = tid + i*256;
        int r = id>>3, seg = id&7;
        CPA16(base + (uint32_t)(r*144 + seg*16),
              g_Qh + ((size_t)bh*NSEQ + row0 + r)*DHEAD + seg*8);
    }
    #pragma unroll
    for (int i=0;i<4;i++){
        int id = tid + i*256;
        int arr = id>>9, rem = id&511, r = rem>>3, seg = rem&7;
        const __half* src = arr ? g_Vh + ((size_t)bh*DHEAD + r)*NSEQ + seg*8
                                : g_Kh + ((size_t)bh*NSEQ + r)*DHEAD + seg*8;
        CPA16(base + (uint32_t)(36864 + arr*9216 + r*144 + seg*16), src);
    }
    CPA_COMMIT();

    float o[2][4][4], ls[2][2];
    #pragma unroll
    for (int mt=0;mt<2;mt++){ ls[mt][0]=0.f; ls[mt][1]=0.f;
        #pragma unroll
        for (int nt=0;nt<4;nt++)
            #pragma unroll
            for (int c=0;c<4;c++) o[mt][nt][c]=0.f; }
    const unsigned* mp[2][2];
    #pragma unroll
    for (int mt=0;mt<2;mt++)
        #pragma unroll
        for (int rh=0;rh<2;rh++)
            mp[mt][rh] = g_maskbits + (size_t)(row0 + wm*32 + mt*16 + rh*8 + gid)*64 + wn;

    CPA_WAIT0();
    __syncthreads();

    for (int t=0;t<32;t++){
        uint32_t cb = 36864u + (uint32_t)(t&1)*18432u;
        // hoist mask loads: hidden behind QK MMAs
        unsigned w0a = mp[0][0][t*2], w1a = mp[0][1][t*2];
        unsigned w0b = mp[1][0][t*2], w1b = mp[1][1][t*2];
        if (t<31){
            uint32_t nb = 36864u + (uint32_t)((t+1)&1)*18432u;
            #pragma unroll
            for (int i=0;i<4;i++){
                int id = tid + i*256;
                int arr = id>>9, rem = id&511, r = rem>>3, seg = rem&7;
                const __half* src = arr ? g_Vh + ((size_t)bh*DHEAD + r)*NSEQ + (t+1)*64 + seg*8
                                        : g_Kh + ((size_t)bh*NSEQ + (t+1)*64 + r)*DHEAD + seg*8;
                CPA16(base + nb + (uint32_t)(arr*9216 + r*144 + seg*16), src);
            }
            CPA_COMMIT();
        }
        float s[2][4][4];
        #pragma unroll
        for (int mt=0;mt<2;mt++)
            #pragma unroll
            for (int nt=0;nt<4;nt++)
                #pragma unroll
                for (int c=0;c<4;c++) s[mt][nt][c]=0.f;
        #pragma unroll
        for (int ks=0;ks<4;ks++){
            uint32_t qh[2][4], kh[8];
            #pragma unroll
            for (int mt=0;mt<2;mt++)
                ldA(qh[mt], base, wm*32+mt*16, ks*16, 72);
            #pragma unroll
            for (int n2=0;n2<2;n2++)
                ldB(kh+n2*4, base+cb, wn*32+n2*16, ks*16, 72);
            #pragma unroll
            for (int mt=0;mt<2;mt++)
                #pragma unroll
                for (int nt=0;nt<4;nt++)
                    MMA(s[mt][nt], qh[mt], kh+nt*2);
        }
        // mask + f16x2 exp2 + P to smem + partial row sums
        #pragma unroll
        for (int mt=0;mt<2;mt++){
            unsigned w0 = mt ? w0b : w0a;
            unsigned w1 = mt ? w1b : w1a;
            int r0 = wm*32 + mt*16 + gid;
            #pragma unroll
            for (int nt=0;nt<4;nt++){
                int bb = nt*8 + tig*2;
                uint32_t p01 = exp2h2(s[mt][nt][0], s[mt][nt][1]);
                if ((w0>>bb)&1u)     p01 &= 0xFFFF0000u;
                if ((w0>>(bb+1))&1u) p01 &= 0x0000FFFFu;
                uint32_t p23 = exp2h2(s[mt][nt][2], s[mt][nt][3]);
                if ((w1>>bb)&1u)     p23 &= 0xFFFF0000u;
                if ((w1>>(bb+1))&1u) p23 &= 0x0000FFFFu;
                float2 f01 = __half22float2(*(__half2*)&p01);
                float2 f23 = __half22float2(*(__half2*)&p23);
                ls[mt][0] += f01.x + f01.y;
                ls[mt][1] += f23.x + f23.y;
                int col = wn*32 + nt*8 + tig*2;
                *(uint32_t*)(sh + 9216 + r0*72 + col)     = p01;
                *(uint32_t*)(sh + 9216 + (r0+8)*72 + col) = p23;
            }
        }
        __syncthreads();
        #pragma unroll
        for (int ks=0;ks<4;ks++){
            uint32_t pa[2][4], vh[8];
            #pragma unroll
            for (int mt=0;mt<2;mt++)
                ldA(pa[mt], base+18432, wm*32+mt*16, ks*16, 72);
            #pragma unroll
            for (int n2=0;n2<2;n2++)
                ldB(vh+n2*4, base+cb+9216, wn*32+n2*16, ks*16, 72);
            #pragma unroll
            for (int mt=0;mt<2;mt++)
                #pragma unroll
                for (int nt=0;nt<4;nt++)
                    MMA(o[mt][nt], pa[mt], vh+nt*2);
        }
        if (t<31) CPA_WAIT0();
        __syncthreads();
    }
    #pragma unroll
    for (int mt=0;mt<2;mt++)
        #pragma unroll
        for (int rh=0;rh<2;rh++){
            ls[mt][rh] += __shfl_xor_sync(0xffffffffu, ls[mt][rh], 1);
            ls[mt][rh] += __shfl_xor_sync(0xffffffffu, ls[mt][rh], 2);
        }
    float* lbuf = (float*)sh;
    if (tig==0){
        #pragma unroll
        for (int mt=0;mt<2;mt++)
            #pragma unroll
            for (int rh=0;rh<2;rh++)
                lbuf[wn*128 + wm*32 + mt*16 + rh*8 + gid] = ls[mt][rh];
    }
    __syncthreads();
    float inv[2][2];
    #pragma unroll
    for (int mt=0;mt<2;mt++)
        #pragma unroll
        for (int rh=0;rh<2;rh++){
            int r = wm*32 + mt*16 + rh*8 + gid;
            inv[mt][rh] = 1.0f / fmaxf(lbuf[r] + lbuf[128+r], 1e-30f);
        }
    #pragma unroll
    for (int mt=0;mt<2;mt++)
        #pragma unroll
        for (int nt=0;nt<4;nt++){
            int d0 = wn*32 + nt*8 + tig*2;
            #pragma unroll
            for (int rh=0;rh<2;rh++){
                float v0 = o[mt][nt][rh*2+0]*inv[mt][rh];
                float v1 = o[mt][nt][rh*2+1]*inv[mt][rh];
                int row = row0 + wm*32 + mt*16 + rh*8 + gid;
                size_t off = ((size_t)b*NSEQ + row)*CDIM + hq*64 + d0;
                *(uint32_t*)(g_Ch+off) = pk2(v0,v1);
            }
        }
}

// ---------------- launch ----------------
extern "C" void kernel_launch(void* const* d_in, const int* in_sizes, int n_in,
                              void* d_out, int out_size){
    const float* x      = (const float*)d_in[0];
    const void*  mask   = d_in[1];
    const float* w_qkv  = (const float*)d_in[2];
    const float* w_proj = (const float*)d_in[3];
    const float* b_proj = (const float*)d_in[4];
    float* out = (float*)d_out;

    cudaFuncSetAttribute(attn_hm, cudaFuncAttributeMaxDynamicSharedMemorySize, ATTN_SMEM);
    cudaFuncSetAttribute(gemm_qkv, cudaFuncAttributeMaxDynamicSharedMemorySize, QKV_SMEM);
    cudaFuncSetAttribute(gemm_proj, cudaFuncAttributeMaxDynamicSharedMemorySize, PROJ_SMEM);

    probe_mask<<<1, 256>>>((const unsigned*)mask);
    mask_pack<<<512, 256>>>(mask);
    splitx<<<6144, 256>>>(x);
    wprep<<<dim3(72,24), dim3(32,8)>>>(w_qkv, 768, 2304, 0);
    wprep<<<dim3(24,24), dim3(32,8)>>>(w_proj, 768, 768, 1);
    gemm_qkv<<<dim3(36,64), 256, QKV_SMEM>>>();
    attn_hm<<<dim3(16,48), 256, ATTN_SMEM>>>();
    gemm_proj<<<dim3(12,64), 256, PROJ_SMEM>>>(b_proj, out);
}

// round 17
// speedup vs baseline: 3.2240x; 1.1792x over previous
#include <cuda_runtime.h>
#include <cuda_fp16.h>
#include <cstdint>

#define BB 4
#define NSEQ 2048
#define CDIM 768
#define HNUM 12
#define DHEAD 64
#define QSE 0.18033688011112042f   // 0.125 * log2(e)

// ---------------- scratch ----------------
__device__ unsigned g_maskbits[NSEQ * (NSEQ / 32)];
__device__ int g_mask_mode;
__device__ __half g_xh[8192*768];
__device__ __half g_wqh[2304*768];
__device__ __half g_wph[768*768],  g_wpl[768*768];
__device__ __half g_Qh[48*2048*64];
__device__ __half g_Kh[48*2048*64];
__device__ __half g_Vh[48*64*2048];
__device__ __half g_Ch[8192*768];

// ---------------- helpers ----------------
__device__ __forceinline__ uint32_t smem_u32(const void* p){
    uint32_t a; asm("{ .reg .u64 t; cvta.to.shared.u64 t, %1; cvt.u32.u64 %0, t; }":"=r"(a):"l"(p)); return a;
}
__device__ __forceinline__ uint32_t pk2(float a, float b){ __half2 h=__floats2half2_rn(a,b); return *(uint32_t*)&h; }
// packed fp16x2: clamp at 14.0 then exp2
__device__ __forceinline__ uint32_t exp2h2p(uint32_t u){
    asm("min.f16x2 %0, %0, %1;" : "+r"(u) : "r"(0x4B004B00u));
    asm("ex2.approx.f16x2 %0, %0;" : "+r"(u));
    return u;
}

#define CPA16(dst, src) asm volatile("cp.async.cg.shared.global [%0], [%1], 16;\n"::"r"(dst),"l"(src):"memory")
#define CPA_COMMIT()    asm volatile("cp.async.commit_group;\n":::"memory")
#define CPA_WAIT0()     asm volatile("cp.async.wait_group 0;\n":::"memory")

#define LDSM4(r0,r1,r2,r3,ad) asm volatile("ldmatrix.sync.aligned.m8n8.x4.shared.b16 {%0,%1,%2,%3},[%4];":"=r"(r0),"=r"(r1),"=r"(r2),"=r"(r3):"r"(ad))
#define MMA(d,a,b) asm volatile("mma.sync.aligned.m16n8k16.row.col.f32.f16.f16.f32 {%0,%1,%2,%3},{%4,%5,%6,%7},{%8,%9},{%0,%1,%2,%3};" \
    :"+f"((d)[0]),"+f"((d)[1]),"+f"((d)[2]),"+f"((d)[3]) \
    :"r"((a)[0]),"r"((a)[1]),"r"((a)[2]),"r"((a)[3]),"r"((b)[0]),"r"((b)[1]))
// fp16-accumulator variant (D,C packed half2 x2)
#define MMAH(d,a,b) asm volatile("mma.sync.aligned.m16n8k16.row.col.f16.f16.f16.f16 {%0,%1},{%2,%3,%4,%5},{%6,%7},{%0,%1};" \
    :"+r"((d)[0]),"+r"((d)[1]) \
    :"r"((a)[0]),"r"((a)[1]),"r"((a)[2]),"r"((a)[3]),"r"((b)[0]),"r"((b)[1]))

__device__ __forceinline__ void ldA(uint32_t* a, uint32_t base, int rb, int kc, int P){
    int l = threadIdx.x & 31;
    uint32_t ad = base + (uint32_t)((rb + (l&7) + ((l>>3)&1)*8)*P + kc + (l>>4)*8)*2;
    LDSM4(a[0],a[1],a[2],a[3],ad);
}
__device__ __forceinline__ void ldB(uint32_t* b, uint32_t base, int nb, int kc, int P){
    int l = threadIdx.x & 31;
    uint32_t ad = base + (uint32_t)((nb + (l&7) + (l>>4)*8)*P + kc + ((l>>3)&1)*8)*2;
    LDSM4(b[0],b[1],b[2],b[3],ad);
}

// ---------------- mask probe + pack ----------------
__global__ void probe_mask(const unsigned* __restrict__ mw) {
    __shared__ int s_not01, s_notfloat;
    int tid = threadIdx.x;
    if (tid == 0) { s_not01 = 0; s_notfloat = 0; }
    __syncthreads();
    unsigned v = mw[tid];
    if (v != 0u && v != 1u) s_not01 = 1;
    if (v != 0u && v != 0x3F800000u) s_notfloat = 1;
    __syncthreads();
    if (tid == 0) g_mask_mode = (!s_not01) ? 0 : (!s_notfloat ? 1 : 2);
}
__global__ void mask_pack(const void* __restrict__ mask) {
    int gid = blockIdx.x * 256 + threadIdx.x;
    if (gid >= NSEQ * (NSEQ / 32)) return;
    long base = (long)(gid >> 6) * NSEQ + (long)(gid & 63) * 32;
    int mode = g_mask_mode;
    unsigned bits = 0u;
    if (mode == 0) {
        const int* p = (const int*)mask;
        #pragma unroll
        for (int j = 0; j < 32; j++) if (p[base + j] != 0) bits |= (1u << j);
    } else if (mode == 1) {
        const float* p = (const float*)mask;
        #pragma unroll
        for (int j = 0; j < 32; j++) if (p[base + j] != 0.0f) bits |= (1u << j);
    } else {
        const unsigned char* p = (const unsigned char*)mask;
        #pragma unroll
        for (int j = 0; j < 32; j++) if (p[base + j] != 0) bits |= (1u << j);
    }
    g_maskbits[gid] = bits;
}

// ---------------- round x to fp16 ----------------
__global__ void splitx(const float* __restrict__ x){
    size_t i = ((size_t)blockIdx.x*256 + threadIdx.x)*4;
    float4 v = *(const float4*)(x + i);
    uint2 hv; hv.x = pk2(v.x, v.y); hv.y = pk2(v.z, v.w);
    *(uint2*)(g_xh + i) = hv;
}
__global__ void wprep(const float* __restrict__ W, int K, int N, int sel){
    __shared__ float t[32][33];
    int k0 = blockIdx.y*32, n0 = blockIdx.x*32;
    int tx = threadIdx.x, ty = threadIdx.y;
    #pragma unroll
    for (int i=0;i<4;i++) t[ty+i*8][tx] = W[(size_t)(k0+ty+i*8)*N + n0+tx];
    __syncthreads();
    #pragma unroll
    for (int i=0;i<4;i++){
        float v = t[tx][ty+i*8];
        size_t o = (size_t)(n0+ty+i*8)*K + k0+tx;
        if (sel){
            __half h = __float2half_rn(v);
            g_wph[o] = h; g_wpl[o] = __float2half_rn(v - __half2float(h));
        } else {
            g_wqh[o] = __float2half_rn(v);
        }
    }
}

// ---------------- HMMA qkv GEMM: 1-pass, k-chunk 64, double-buffered -------
#define QKV_SMEM (55296)
__global__ __launch_bounds__(256) void gemm_qkv(){
    extern __shared__ __half smq[];
    int tid = threadIdx.x, wid = tid>>5, lane = tid&31;
    int wm = wid>>1, wn = wid&1, gid = lane>>2, tig = lane&3;
    int m0 = blockIdx.y*128, n0 = blockIdx.x*64;
    uint32_t base = smem_u32(smq);
    float s[2][4][4];
    #pragma unroll
    for (int a=0;a<2;a++)
        #pragma unroll
        for (int b=0;b<4;b++)
            #pragma unroll
            for (int c=0;c<4;c++) s[a][b][c]=0.f;

    #pragma unroll
    for (int i=0;i<4;i++){
        int id = tid + i*256;
        int r = id>>3, seg = id&7;
        CPA16(base + (uint32_t)(r*144 + seg*16), g_xh + (size_t)(m0+r)*768 + seg*8);
    }
    #pragma unroll
    for (int i=0;i<2;i++){
        int id = tid + i*256;
        int r = id>>3, seg = id&7;
        CPA16(base + (uint32_t)(18432 + r*144 + seg*16), g_wqh + (size_t)(n0+r)*768 + seg*8);
    }
    CPA_COMMIT();

    for (int k=0;k<12;k++){
        uint32_t bb = (uint32_t)(k&1)*27648u;
        CPA_WAIT0();
        __syncthreads();
        if (k<11){
            uint32_t nb = (uint32_t)((k+1)&1)*27648u;
            int k0 = (k+1)*64;
            #pragma unroll
            for (int i=0;i<4;i++){
                int id = tid + i*256;
                int r = id>>3, seg = id&7;
                CPA16(base + nb + (uint32_t)(r*144 + seg*16),
                      g_xh + (size_t)(m0+r)*768 + k0 + seg*8);
            }
            #pragma unroll
            for (int i=0;i<2;i++){
                int id = tid + i*256;
                int r = id>>3, seg = id&7;
                CPA16(base + nb + (uint32_t)(18432 + r*144 + seg*16),
                      g_wqh + (size_t)(n0+r)*768 + k0 + seg*8);
            }
            CPA_COMMIT();
        }
        #pragma unroll
        for (int ks=0;ks<4;ks++){
            uint32_t ah[2][4], bh[8];
            #pragma unroll
            for (int mt=0;mt<2;mt++)
                ldA(ah[mt], base+bb, wm*32+mt*16, ks*16, 72);
            #pragma unroll
            for (int n2=0;n2<2;n2++)
                ldB(bh+n2*4, base+bb+18432, wn*32+n2*16, ks*16, 72);
            #pragma unroll
            for (int mt=0;mt<2;mt++)
                #pragma unroll
                for (int nt=0;nt<4;nt++)
                    MMA(s[mt][nt], ah[mt], bh+nt*2);
        }
        __syncthreads();
    }
    int which = n0/768, rem = n0 - which*768;
    int bhq = (m0>>11)*HNUM + (rem>>6);
    int tok0 = m0 & 2047;
    #pragma unroll
    for (int mt=0;mt<2;mt++)
        #pragma unroll
        for (int nt=0;nt<4;nt++){
            int d0 = wn*32 + nt*8 + tig*2;
            if (which==2){
                #pragma unroll
                for (int c=0;c<4;c++){
                    int tok = tok0 + wm*32 + mt*16 + (c>>1)*8 + gid;
                    int d = d0 + (c&1);
                    g_Vh[((size_t)bhq*DHEAD + d)*NSEQ + tok] = __float2half_rn(s[mt][nt][c]);
                }
            } else {
                float sc = (which==0) ? QSE : 1.0f;
                __half* Ah = (which==0) ? g_Qh : g_Kh;
                #pragma unroll
                for (int rh=0;rh<2;rh++){
                    int tok = tok0 + wm*32 + mt*16 + rh*8 + gid;
                    size_t o = ((size_t)bhq*NSEQ + tok)*DHEAD + d0;
                    *(uint32_t*)(Ah+o) = pk2(s[mt][nt][rh*2+0]*sc, s[mt][nt][rh*2+1]*sc);
                }
            }
        }
}

// ---------------- HMMA proj GEMM: 2-pass, k-chunk 64, double-buffered ------
#define PROJ_SMEM (73728)
__global__ __launch_bounds__(256) void gemm_proj(const float* __restrict__ bias,
                                                 float* __restrict__ Out){
    extern __shared__ __half smp[];
    int tid = threadIdx.x, wid = tid>>5, lane = tid&31;
    int wm = wid>>1, wn = wid&1, gid = lane>>2, tig = lane&3;
    int m0 = blockIdx.y*128, n0 = blockIdx.x*64;
    uint32_t base = smem_u32(smp);
    float s[2][4][4];
    #pragma unroll
    for (int a=0;a<2;a++)
        #pragma unroll
        for (int b=0;b<4;b++)
            #pragma unroll
            for (int c=0;c<4;c++) s[a][b][c]=0.f;

    #pragma unroll
    for (int i=0;i<4;i++){
        int id = tid + i*256;
        int r = id>>3, seg = id&7;
        CPA16(base + (uint32_t)(r*144 + seg*16), g_Ch + (size_t)(m0+r)*768 + seg*8);
    }
    #pragma unroll
    for (int i=0;i<2;i++){
        int id = tid + i*256;
        int r = id>>3, seg = id&7;
        CPA16(base + (uint32_t)(18432 + r*144 + seg*16), g_wph + (size_t)(n0+r)*768 + seg*8);
        CPA16(base + (uint32_t)(27648 + r*144 + seg*16), g_wpl + (size_t)(n0+r)*768 + seg*8);
    }
    CPA_COMMIT();

    for (int k=0;k<12;k++){
        uint32_t bb = (uint32_t)(k&1)*36864u;
        CPA_WAIT0();
        __syncthreads();
        if (k<11){
            uint32_t nb = (uint32_t)((k+1)&1)*36864u;
            int k0 = (k+1)*64;
            #pragma unroll
            for (int i=0;i<4;i++){
                int id = tid + i*256;
                int r = id>>3, seg = id&7;
                CPA16(base + nb + (uint32_t)(r*144 + seg*16),
                      g_Ch + (size_t)(m0+r)*768 + k0 + seg*8);
            }
            #pragma unroll
            for (int i=0;i<2;i++){
                int id = tid + i*256;
                int r = id>>3, seg = id&7;
                CPA16(base + nb + (uint32_t)(18432 + r*144 + seg*16),
                      g_wph + (size_t)(n0+r)*768 + k0 + seg*8);
                CPA16(base + nb + (uint32_t)(27648 + r*144 + seg*16),
                      g_wpl + (size_t)(n0+r)*768 + k0 + seg*8);
            }
            CPA_COMMIT();
        }
        #pragma unroll
        for (int ks=0;ks<4;ks++){
            uint32_t ah[2][4], bh[8], bl[8];
            #pragma unroll
            for (int mt=0;mt<2;mt++)
                ldA(ah[mt], base+bb, wm*32+mt*16, ks*16, 72);
            #pragma unroll
            for (int n2=0;n2<2;n2++){
                ldB(bh+n2*4, base+bb+18432, wn*32+n2*16, ks*16, 72);
                ldB(bl+n2*4, base+bb+27648, wn*32+n2*16, ks*16, 72);
            }
            #pragma unroll
            for (int mt=0;mt<2;mt++)
                #pragma unroll
                for (int nt=0;nt<4;nt++){
                    MMA(s[mt][nt], ah[mt], bh+nt*2);
                    MMA(s[mt][nt], ah[mt], bl+nt*2);
                }
        }
        __syncthreads();
    }
    #pragma unroll
    for (int mt=0;mt<2;mt++)
        #pragma unroll
        for (int nt=0;nt<4;nt++)
            #pragma unroll
            for (int c=0;c<4;c++){
                int row = m0 + wm*32 + mt*16 + (c>>1)*8 + gid;
                int col = n0 + wn*32 + nt*8 + tig*2 + (c&1);
                Out[(size_t)row*768 + col] = s[mt][nt][c] + bias[col];
            }
}

// ---------------- HMMA attention: fp16-accum QK, f16x2 exp, 3 CTAs/SM ------
#define ATTN_SMEM (73728)
__global__ __launch_bounds__(256, 3) void attn_hm(){
    extern __shared__ __half sh[];
    uint32_t base = smem_u32(sh);
    int tid = threadIdx.x, wid = tid>>5, lane = tid&31;
    int wm = wid>>1, wn = wid&1, gid = lane>>2, tig = lane&3;
    int bh = blockIdx.y, b = bh/HNUM, hq = bh - b*HNUM;
    int row0 = blockIdx.x*128;

    #pragma unroll
    for (int i=0;i<4;i++){
        int id = tid + i*256;
        int r = id>>3, seg = id&7;
        CPA16(base + (uint32_t)(r*144 + seg*16),
              g_Qh + ((size_t)bh*NSEQ + row0 + r)*DHEAD + seg*8);
    }
    #pragma unroll
    for (int i=0;i<4;i++){
        int id = tid + i*256;
        int arr = id>>9, rem = id&511, r = rem>>3, seg = rem&7;
        const __half* src = arr ? g_Vh + ((size_t)bh*DHEAD + r)*NSEQ + seg*8
                                : g_Kh + ((size_t)bh*NSEQ + r)*DHEAD + seg*8;
        CPA16(base + (uint32_t)(36864 + arr*9216 + r*144 + seg*16), src);
    }
    CPA_COMMIT();

    float o[2][4][4], ls[2][2];
    #pragma unroll
    for (int mt=0;mt<2;mt++){ ls[mt][0]=0.f; ls[mt][1]=0.f;
        #pragma unroll
        for (int nt=0;nt<4;nt++)
            #pragma unroll
            for (int c=0;c<4;c++) o[mt][nt][c]=0.f; }
    const unsigned* mp[2][2];
    #pragma unroll
    for (int mt=0;mt<2;mt++)
        #pragma unroll
        for (int rh=0;rh<2;rh++)
            mp[mt][rh] = g_maskbits + (size_t)(row0 + wm*32 + mt*16 + rh*8 + gid)*64 + wn;

    CPA_WAIT0();
    __syncthreads();

    for (int t=0;t<32;t++){
        uint32_t cb = 36864u + (uint32_t)(t&1)*18432u;
        unsigned w0a = mp[0][0][t*2], w1a = mp[0][1][t*2];
        unsigned w0b = mp[1][0][t*2], w1b = mp[1][1][t*2];
        if (t<31){
            uint32_t nb = 36864u + (uint32_t)((t+1)&1)*18432u;
            #pragma unroll
            for (int i=0;i<4;i++){
                int id = tid + i*256;
                int arr = id>>9, rem = id&511, r = rem>>3, seg = rem&7;
                const __half* src = arr ? g_Vh + ((size_t)bh*DHEAD + r)*NSEQ + (t+1)*64 + seg*8
                                        : g_Kh + ((size_t)bh*NSEQ + (t+1)*64 + r)*DHEAD + seg*8;
                CPA16(base + nb + (uint32_t)(arr*9216 + r*144 + seg*16), src);
            }
            CPA_COMMIT();
        }
        // S = Q K^T in fp16 accum (packed D fragments)
        uint32_t s16[2][4][2];
        #pragma unroll
        for (int mt=0;mt<2;mt++)
            #pragma unroll
            for (int nt=0;nt<4;nt++){ s16[mt][nt][0]=0u; s16[mt][nt][1]=0u; }
        #pragma unroll
        for (int ks=0;ks<4;ks++){
            uint32_t qh[2][4], kh[8];
            #pragma unroll
            for (int mt=0;mt<2;mt++)
                ldA(qh[mt], base, wm*32+mt*16, ks*16, 72);
            #pragma unroll
            for (int n2=0;n2<2;n2++)
                ldB(kh+n2*4, base+cb, wn*32+n2*16, ks*16, 72);
            #pragma unroll
            for (int mt=0;mt<2;mt++)
                #pragma unroll
                for (int nt=0;nt<4;nt++)
                    MMAH(s16[mt][nt], qh[mt], kh+nt*2);
        }
        // mask + packed exp2 + P to smem + partial row sums
        #pragma unroll
        for (int mt=0;mt<2;mt++){
            unsigned w0 = mt ? w0b : w0a;
            unsigned w1 = mt ? w1b : w1a;
            int r0 = wm*32 + mt*16 + gid;
            #pragma unroll
            for (int nt=0;nt<4;nt++){
                int bb = nt*8 + tig*2;
                uint32_t p01 = exp2h2p(s16[mt][nt][0]);
                if ((w0>>bb)&1u)     p01 &= 0xFFFF0000u;
                if ((w0>>(bb+1))&1u) p01 &= 0x0000FFFFu;
                uint32_t p23 = exp2h2p(s16[mt][nt][1]);
                if ((w1>>bb)&1u)     p23 &= 0xFFFF0000u;
                if ((w1>>(bb+1))&1u) p23 &= 0x0000FFFFu;
                float2 f01 = __half22float2(*(__half2*)&p01);
                float2 f23 = __half22float2(*(__half2*)&p23);
                ls[mt][0] += f01.x + f01.y;
                ls[mt][1] += f23.x + f23.y;
                int col = wn*32 + nt*8 + tig*2;
                *(uint32_t*)(sh + 9216 + r0*72 + col)     = p01;
                *(uint32_t*)(sh + 9216 + (r0+8)*72 + col) = p23;
            }
        }
        __syncthreads();
        // O += P V (fp32 accum — output path)
        #pragma unroll
        for (int ks=0;ks<4;ks++){
            uint32_t pa[2][4], vh[8];
            #pragma unroll
            for (int mt=0;mt<2;mt++)
                ldA(pa[mt], base+18432, wm*32+mt*16, ks*16, 72);
            #pragma unroll
            for (int n2=0;n2<2;n2++)
                ldB(vh+n2*4, base+cb+9216, wn*32+n2*16, ks*16, 72);
            #pragma unroll
            for (int mt=0;mt<2;mt++)
                #pragma unroll
                for (int nt=0;nt<4;nt++)
                    MMA(o[mt][nt], pa[mt], vh+nt*2);
        }
        if (t<31) CPA_WAIT0();
        __syncthreads();
    }
    #pragma unroll
    for (int mt=0;mt<2;mt++)
        #pragma unroll
        for (int rh=0;rh<2;rh++){
            ls[mt][rh] += __shfl_xor_sync(0xffffffffu, ls[mt][rh], 1);
            ls[mt][rh] += __shfl_xor_sync(0xffffffffu, ls[mt][rh], 2);
        }
    float* lbuf = (float*)sh;
    if (tig==0){
        #pragma unroll
        for (int mt=0;mt<2;mt++)
            #pragma unroll
            for (int rh=0;rh<2;rh++)
                lbuf[wn*128 + wm*32 + mt*16 + rh*8 + gid] = ls[mt][rh];
    }
    __syncthreads();
    float inv[2][2];
    #pragma unroll
    for (int mt=0;mt<2;mt++)
        #pragma unroll
        for (int rh=0;rh<2;rh++){
            int r = wm*32 + mt*16 + rh*8 + gid;
            inv[mt][rh] = 1.0f / fmaxf(lbuf[r] + lbuf[128+r], 1e-30f);
        }
    #pragma unroll
    for (int mt=0;mt<2;mt++)
        #pragma unroll
        for (int nt=0;nt<4;nt++){
            int d0 = wn*32 + nt*8 + tig*2;
            #pragma unroll
            for (int rh=0;rh<2;rh++){
                float v0 = o[mt][nt][rh*2+0]*inv[mt][rh];
                float v1 = o[mt][nt][rh*2+1]*inv[mt][rh];
                int row = row0 + wm*32 + mt*16 + rh*8 + gid;
                size_t off = ((size_t)b*NSEQ + row)*CDIM + hq*64 + d0;
                *(uint32_t*)(g_Ch+off) = pk2(v0,v1);
            }
        }
}

// ---------------- launch ----------------
extern "C" void kernel_launch(void* const* d_in, const int* in_sizes, int n_in,
                              void* d_out, int out_size){
    const float* x      = (const float*)d_in[0];
    const void*  mask   = d_in[1];
    const float* w_qkv  = (const float*)d_in[2];
    const float* w_proj = (const float*)d_in[3];
    const float* b_proj = (const float*)d_in[4];
    float* out = (float*)d_out;

    cudaFuncSetAttribute(attn_hm, cudaFuncAttributeMaxDynamicSharedMemorySize, ATTN_SMEM);
    cudaFuncSetAttribute(gemm_qkv, cudaFuncAttributeMaxDynamicSharedMemorySize, QKV_SMEM);
    cudaFuncSetAttribute(gemm_proj, cudaFuncAttributeMaxDynamicSharedMemorySize, PROJ_SMEM);

    probe_mask<<<1, 256>>>((const unsigned*)mask);
    mask_pack<<<512, 256>>>(mask);
    splitx<<<6144, 256>>>(x);
    wprep<<<dim3(72,24), dim3(32,8)>>>(w_qkv, 768, 2304, 0);
    wprep<<<dim3(24,24), dim3(32,8)>>>(w_proj, 768, 768, 1);
    gemm_qkv<<<dim3(36,64), 256, QKV_SMEM>>>();
    attn_hm<<<dim3(16,48), 256, ATTN_SMEM>>>();
    gemm_proj<<<dim3(12,64), 256, PROJ_SMEM>>>(b_proj, out);
}